// round 5
// baseline (speedup 1.0000x reference)
#include <cuda_runtime.h>
#include <cuda_fp16.h>
#include <math.h>
#include <stdint.h>

#define BB 16384
#define KK 512

// ---------------- scratch (device globals; no allocations) ----------------
__device__ __half g_seq_h[BB * 512];
__device__ __half g_base_p[BB * 512];
__device__ __half g_base_f[BB * 512];
__device__ __half g_h1_p[BB * 512];
__device__ __half g_h1_f[BB * 512];
__device__ __half g_h2_p[BB * 256];
__device__ __half g_h2_f[BB * 512];
__device__ __half g_wt_p1[512 * 512];   // pw1[0:512]^T  [n][k] fp16
__device__ __half g_wt_f1[512 * 512];   // fw1[0:512]^T
__device__ __half g_wt_p2[256 * 512];   // pw2^T
__device__ __half g_wt_f2[512 * 512];   // fw2^T
__device__ float g_pres_state[BB * 6];
__device__ float g_full_state[BB * 12];
__device__ float g_losses[4];  // lf, lp, le, nm

__constant__ int c_perms[6][3] = {
    {0, 1, 2}, {0, 2, 1}, {1, 0, 2}, {1, 2, 0}, {2, 0, 1}, {2, 1, 0}};

__device__ __forceinline__ float gelu_exact(float x) {
    return 0.5f * x * (1.0f + erff(x * 0.7071067811865475f));
}

// ================= PTX helpers (Ampere-era, safe on sm_103) ================
__device__ __forceinline__ uint32_t smem_u32(const void* p) {
    uint32_t a;
    asm("{ .reg .u64 t; cvta.to.shared.u64 t, %1; cvt.u32.u64 %0, t; }"
        : "=r"(a) : "l"(p));
    return a;
}
__device__ __forceinline__ void cp_async16(uint32_t dst, const void* src) {
    asm volatile("cp.async.ca.shared.global [%0], [%1], 16;" ::"r"(dst),
                 "l"(src) : "memory");
}
#define CP_COMMIT() asm volatile("cp.async.commit_group;" ::: "memory")
#define CP_WAIT(n) asm volatile("cp.async.wait_group %0;" ::"n"(n) : "memory")

__device__ __forceinline__ void ldsm_x4(uint32_t* r, uint32_t addr) {
    asm volatile(
        "ldmatrix.sync.aligned.m8n8.x4.shared.b16 {%0,%1,%2,%3}, [%4];"
        : "=r"(r[0]), "=r"(r[1]), "=r"(r[2]), "=r"(r[3])
        : "r"(addr));
}
__device__ __forceinline__ void mma_f16(float* c, const uint32_t* a,
                                        const uint32_t* b) {
    asm volatile(
        "mma.sync.aligned.m16n8k16.row.col.f32.f16.f16.f32 "
        "{%0,%1,%2,%3}, {%4,%5,%6,%7}, {%8,%9}, {%0,%1,%2,%3};"
        : "+f"(c[0]), "+f"(c[1]), "+f"(c[2]), "+f"(c[3])
        : "r"(a[0]), "r"(a[1]), "r"(a[2]), "r"(a[3]), "r"(b[0]), "r"(b[1]));
}

// ---------------- init ------------------------------------------------------
__global__ void init_kernel() {
    int i = blockIdx.x * blockDim.x + threadIdx.x;
    int stride = gridDim.x * blockDim.x;
    const int n = BB * 6 + BB * 12 + 4;
    for (; i < n; i += stride) {
        if (i < BB * 6) g_pres_state[i] = 0.f;
        else if (i < BB * 18) g_full_state[i - BB * 6] = 0.f;
        else g_losses[i - BB * 18] = 0.f;
    }
}

// ---------------- fp32 -> fp16 convert (seq_embed) --------------------------
__global__ void __launch_bounds__(256) convert_seq_kernel(
    const float* __restrict__ src, __half* __restrict__ dst) {
    const int i = (blockIdx.x * 256 + threadIdx.x) * 8;
    float4 v0 = *(const float4*)(src + i);
    float4 v1 = *(const float4*)(src + i + 4);
    __half2 h[4];
    h[0] = __floats2half2_rn(v0.x, v0.y);
    h[1] = __floats2half2_rn(v0.z, v0.w);
    h[2] = __floats2half2_rn(v1.x, v1.y);
    h[3] = __floats2half2_rn(v1.z, v1.w);
    *(uint4*)(dst + i) = *(uint4*)h;
}

// ---------------- weight transpose+convert: dst[n*512+k]=(half)src[k*N+n] ---
__global__ void transpose_kernel(const float* __restrict__ src,
                                 __half* __restrict__ dst, int N) {
    __shared__ float t[32][33];
    const int n0 = blockIdx.x * 32, k0 = blockIdx.y * 32;
#pragma unroll
    for (int i = 0; i < 4; i++)
        t[threadIdx.y + i * 8][threadIdx.x] =
            src[(k0 + threadIdx.y + i * 8) * N + n0 + threadIdx.x];
    __syncthreads();
#pragma unroll
    for (int i = 0; i < 4; i++)
        dst[(n0 + threadIdx.y + i * 8) * 512 + k0 + threadIdx.x] =
            __float2half_rn(t[threadIdx.x][threadIdx.y + i * 8]);
}

// ---------------- fp16 tensor-core GEMM, dual-problem ----------------------
// Computes two independent GEMMs in one grid (branch select on blockIdx.x).
// C[BB,N](fp16) = A[BB,512](fp16) @ Wt^T (Wt [N][512] fp16, K-major) + bias
// BM=128, BN=256, BK=32; 256 threads (8 warps, 2x4), warp tile 64x64.
// cp.async double-buffered; smem rows padded to 80B (conflict-free ldmatrix).
#define SM_BUF 30720   // per stage: A 128*80 + B 256*80
__global__ void __launch_bounds__(256) gemm_dual(
    const __half* __restrict__ Ap, const __half* __restrict__ Wtp,
    const float* __restrict__ biasp, __half* __restrict__ Cp, int Np,
    int nbp, int gelup,
    const __half* __restrict__ Af, const __half* __restrict__ Wtf,
    const float* __restrict__ biasf, __half* __restrict__ Cf, int Nf,
    int geluf)
{
    extern __shared__ __align__(16) unsigned char smraw[];
    const uint32_t sb = smem_u32(smraw);

    int bx = blockIdx.x;
    const __half* A;
    const __half* Wt;
    const float* bias;
    __half* C;
    int N, do_gelu;
    if (bx < nbp) {
        A = Ap; Wt = Wtp; bias = biasp; C = Cp; N = Np; do_gelu = gelup;
    } else {
        bx -= nbp;
        A = Af; Wt = Wtf; bias = biasf; C = Cf; N = Nf; do_gelu = geluf;
    }

    const int tid = threadIdx.x;
    const int lane = tid & 31;
    const int wid = tid >> 5;
    const int warp_m = wid >> 2;   // 0..1
    const int warp_n = wid & 3;    // 0..3
    const int brow = blockIdx.y * 128;
    const int bcol = bx * 256;

    const __half* Ab = A + (size_t)brow * 512;
    const __half* Bb = Wt + (size_t)bcol * 512;

    float acc[4][8][4];
#pragma unroll
    for (int i = 0; i < 4; i++)
#pragma unroll
        for (int j = 0; j < 8; j++)
#pragma unroll
            for (int k = 0; k < 4; k++) acc[i][j][k] = 0.f;

#define LOAD_TILE(cidx, buf)                                                  \
    do {                                                                      \
        const int kc = (cidx) * 32;                                           \
        const uint32_t base = sb + (buf) * SM_BUF;                            \
        _Pragma("unroll")                                                     \
        for (int i = 0; i < 2; i++) {                                         \
            const int lin = tid + i * 256;                                    \
            const int r = lin >> 2, ch = lin & 3;                             \
            cp_async16(base + r * 80 + ch * 16,                               \
                       Ab + (size_t)r * 512 + kc + ch * 8);                   \
        }                                                                     \
        _Pragma("unroll")                                                     \
        for (int i = 0; i < 4; i++) {                                         \
            const int lin = tid + i * 256;                                    \
            const int r = lin >> 2, ch = lin & 3;                             \
            cp_async16(base + 10240 + r * 80 + ch * 16,                       \
                       Bb + (size_t)r * 512 + kc + ch * 8);                   \
        }                                                                     \
    } while (0)

    LOAD_TILE(0, 0);
    CP_COMMIT();

    const uint32_t a_off =
        (uint32_t)(warp_m * 64 + (lane & 15)) * 80 + ((lane >> 4) << 4);
    const uint32_t b_off = 10240 +
        (uint32_t)(warp_n * 64 + ((lane >> 4) << 3) + (lane & 7)) * 80 +
        (((lane >> 3) & 1) << 4);

    for (int c = 0; c < 16; c++) {
        const int buf = c & 1;
        const uint32_t sbuf = sb + buf * SM_BUF;
        if (c < 15) {
            LOAD_TILE(c + 1, buf ^ 1);
            CP_COMMIT();
            CP_WAIT(1);
        } else {
            CP_WAIT(0);
        }
        __syncthreads();

#pragma unroll
        for (int ks = 0; ks < 2; ks++) {
            uint32_t a[4][4], b[8][2];
#pragma unroll
            for (int mf = 0; mf < 4; mf++)
                ldsm_x4(a[mf], sbuf + a_off + mf * (16 * 80) + ks * 32);
#pragma unroll
            for (int g = 0; g < 4; g++) {
                uint32_t r[4];
                ldsm_x4(r, sbuf + b_off + g * (16 * 80) + ks * 32);
                b[g * 2][0] = r[0]; b[g * 2][1] = r[1];
                b[g * 2 + 1][0] = r[2]; b[g * 2 + 1][1] = r[3];
            }
#pragma unroll
            for (int mf = 0; mf < 4; mf++)
#pragma unroll
                for (int nf = 0; nf < 8; nf++)
                    mma_f16(acc[mf][nf], a[mf], b[nf]);
        }
        __syncthreads();
    }

    // epilogue
    const int erow = warp_m * 64 + (lane >> 2);
    const int ecol = warp_n * 64 + (lane & 3) * 2;
#pragma unroll
    for (int nf = 0; nf < 8; nf++) {
        const int col = bcol + ecol + nf * 8;
        const float2 bv = *(const float2*)(bias + col);
#pragma unroll
        for (int mf = 0; mf < 4; mf++) {
            float x0 = acc[mf][nf][0] + bv.x;
            float x1 = acc[mf][nf][1] + bv.y;
            float x2 = acc[mf][nf][2] + bv.x;
            float x3 = acc[mf][nf][3] + bv.y;
            if (do_gelu) {
                x0 = gelu_exact(x0); x1 = gelu_exact(x1);
                x2 = gelu_exact(x2); x3 = gelu_exact(x3);
            }
            const int r0 = brow + erow + mf * 16;
            *(__half2*)(C + (size_t)r0 * N + col) = __floats2half2_rn(x0, x1);
            *(__half2*)(C + (size_t)(r0 + 8) * N + col) =
                __floats2half2_rn(x2, x3);
        }
    }
}

// ---------------- build h1: smem-cached correction weights ------------------
__global__ void __launch_bounds__(256) build_h1_kernel(
    const float* __restrict__ pw1, const float* __restrict__ fw1,
    const int* __restrict__ perm_idx, int step)
{
    __shared__ float wc[24][512];
    const int tid = threadIdx.x;
#pragma unroll
    for (int i = 0; i < 12; i++) {
        const int lin = tid + i * 256;
        const int row = lin >> 7;
        const int c4 = (lin & 127) << 2;
        const float* src = (row < 9) ? (pw1 + (512 + row) * 512 + c4)
                                     : (fw1 + (512 + row - 9) * 512 + c4);
        *(float4*)&wc[row][c4] = *(const float4*)src;
    }
    __syncthreads();

    const int n0 = tid * 2;
#pragma unroll 1
    for (int r = 0; r < 8; r++) {
        const int b = blockIdx.x * 8 + r;
        const int ridx = c_perms[__ldg(&perm_idx[b])][step];
        float ps[6], fs[12];
#pragma unroll
        for (int j = 0; j < 6; j++) ps[j] = __ldg(&g_pres_state[b * 6 + j]);
#pragma unroll
        for (int j = 0; j < 12; j++) fs[j] = __ldg(&g_full_state[b * 12 + j]);

        float2 hp = __half22float2(*(const __half2*)&g_base_p[b * 512 + n0]);
#pragma unroll
        for (int j = 0; j < 6; j++) {
            const float2 w = *(const float2*)&wc[j][n0];
            hp.x = fmaf(ps[j], w.x, hp.x);
            hp.y = fmaf(ps[j], w.y, hp.y);
        }
        {
            const float2 w = *(const float2*)&wc[6 + ridx][n0];
            hp.x += w.x; hp.y += w.y;
        }
        hp.x = gelu_exact(hp.x); hp.y = gelu_exact(hp.y);
        *(__half2*)&g_h1_p[b * 512 + n0] = __floats2half2_rn(hp.x, hp.y);

        float2 hf = __half22float2(*(const __half2*)&g_base_f[b * 512 + n0]);
#pragma unroll
        for (int j = 0; j < 12; j++) {
            const float2 w = *(const float2*)&wc[9 + j][n0];
            hf.x = fmaf(fs[j], w.x, hf.x);
            hf.y = fmaf(fs[j], w.y, hf.y);
        }
        {
            const float2 w = *(const float2*)&wc[21 + ridx][n0];
            hf.x += w.x; hf.y += w.y;
        }
        hf.x = gelu_exact(hf.x); hf.y = gelu_exact(hf.y);
        *(__half2*)&g_h1_f[b * 512 + n0] = __floats2half2_rn(hf.x, hf.y);
    }
}

// ---------------- head (3rd layer dots) + losses + state update -------------
__global__ void __launch_bounds__(256) head_update_kernel(
    const float* __restrict__ pw3, const float* __restrict__ pb3,
    const float* __restrict__ fw3, const float* __restrict__ fb3,
    const float* __restrict__ freq, const float* __restrict__ pres,
    const float* __restrict__ enrich, const int* __restrict__ perm_idx,
    const int* __restrict__ round_mask, float* __restrict__ out, int step)
{
    __shared__ float blk[4];
    const int tid = threadIdx.x;
    const int lane = tid & 31;
    const int w = tid >> 5;
    if (tid < 4) blk[tid] = 0.f;
    __syncthreads();

    const int b = blockIdx.x * 8 + w;
    float pp = 0.f, pf = 0.f, pe = 0.f;
    const __half2* hp = (const __half2*)(g_h2_p + b * 256);
    const __half2* hf = (const __half2*)(g_h2_f + b * 512);

#pragma unroll
    for (int m = lane; m < 128; m += 32) {
        const float2 v = __half22float2(hp[m]);
        const float2 wv = *(const float2*)&pw3[2 * m];
        pp = fmaf(v.x, wv.x, pp);
        pp = fmaf(v.y, wv.y, pp);
    }
#pragma unroll
    for (int m = lane; m < 256; m += 32) {
        const float2 v = __half22float2(hf[m]);
        const float4 f3 = *(const float4*)&fw3[4 * m];
        pf = fmaf(v.x, f3.x, pf);
        pe = fmaf(v.x, f3.y, pe);
        pf = fmaf(v.y, f3.z, pf);
        pe = fmaf(v.y, f3.w, pe);
    }
#pragma unroll
    for (int o = 16; o > 0; o >>= 1) {
        pp += __shfl_xor_sync(0xffffffffu, pp, o);
        pf += __shfl_xor_sync(0xffffffffu, pf, o);
        pe += __shfl_xor_sync(0xffffffffu, pe, o);
    }

    if (lane == 0) {
        pp += pb3[0];
        pf += fb3[0];
        pe += fb3[1];
        const int ridx = c_perms[perm_idx[b]][step];
        const float m = (float)round_mask[b * 3 + ridx];
        const float gt_f = freq[b * 3 + ridx];
        const float gt_p = pres[b * 3 + ridx];
        const float gt_e = enrich[b * 3 + ridx];

        const float dlf = (pf - gt_f) * (pf - gt_f) * m;
        const float bce = fmaxf(pp, 0.f) - pp * gt_p + log1pf(expf(-fabsf(pp)));
        const float dlp = bce * m;
        const float dle = (pe - gt_e) * (pe - gt_e) * m;

        const bool msk = m > 0.5f;
        const float act_f = msk ? fminf(fmaxf(pf, -10.f), 10.f) : gt_f;
        const float act_p = msk ? (1.f / (1.f + expf(-pp))) : gt_p;
        const float act_e = msk ? fminf(fmaxf(pe, -100.f), 100.f) : gt_e;

        g_pres_state[b * 6 + 2 * ridx + 0] = act_p;
        g_pres_state[b * 6 + 2 * ridx + 1] = 1.f;
        g_full_state[b * 12 + 4 * ridx + 0] = act_f;
        g_full_state[b * 12 + 4 * ridx + 1] = act_p;
        g_full_state[b * 12 + 4 * ridx + 2] = act_e;
        g_full_state[b * 12 + 4 * ridx + 3] = 1.f;

        out[3 + b * 3 + ridx] = act_f;
        out[3 + 3 * BB + b * 3 + ridx] = act_p;
        out[3 + 6 * BB + b * 3 + ridx] = act_e;

        atomicAdd(&blk[0], dlf);
        atomicAdd(&blk[1], dlp);
        atomicAdd(&blk[2], dle);
        atomicAdd(&blk[3], m);
    }
    __syncthreads();
    if (tid < 4) atomicAdd(&g_losses[tid], blk[tid]);
}

__global__ void finalize_kernel(float* __restrict__ out) {
    if (threadIdx.x == 0 && blockIdx.x == 0) {
        const float nm = g_losses[3] + 1e-8f;
        out[0] = g_losses[0] / nm;
        out[1] = g_losses[1] / nm;
        out[2] = g_losses[2] / nm;
    }
}

// ---------------- launcher --------------------------------------------------
extern "C" void kernel_launch(void* const* d_in, const int* in_sizes, int n_in,
                              void* d_out, int out_size)
{
    const float* seq      = (const float*)d_in[0];
    const float* freq     = (const float*)d_in[1];
    const float* pres     = (const float*)d_in[2];
    const float* enrich   = (const float*)d_in[3];
    const float* pw1      = (const float*)d_in[4];
    const float* pb1      = (const float*)d_in[5];
    const float* pw2      = (const float*)d_in[6];
    const float* pb2      = (const float*)d_in[7];
    const float* pw3      = (const float*)d_in[8];
    const float* pb3      = (const float*)d_in[9];
    const float* fw1      = (const float*)d_in[10];
    const float* fb1      = (const float*)d_in[11];
    const float* fw2      = (const float*)d_in[12];
    const float* fb2      = (const float*)d_in[13];
    const float* fw3      = (const float*)d_in[14];
    const float* fb3      = (const float*)d_in[15];
    const int*   perm_idx = (const int*)d_in[16];
    const int*   rmask    = (const int*)d_in[17];
    float* out = (float*)d_out;

    __half *seq_h, *base_p, *base_f, *h1_p, *h1_f, *h2_p, *h2_f;
    __half *wt_p1, *wt_f1, *wt_p2, *wt_f2;
    cudaGetSymbolAddress((void**)&seq_h, g_seq_h);
    cudaGetSymbolAddress((void**)&base_p, g_base_p);
    cudaGetSymbolAddress((void**)&base_f, g_base_f);
    cudaGetSymbolAddress((void**)&h1_p, g_h1_p);
    cudaGetSymbolAddress((void**)&h1_f, g_h1_f);
    cudaGetSymbolAddress((void**)&h2_p, g_h2_p);
    cudaGetSymbolAddress((void**)&h2_f, g_h2_f);
    cudaGetSymbolAddress((void**)&wt_p1, g_wt_p1);
    cudaGetSymbolAddress((void**)&wt_f1, g_wt_f1);
    cudaGetSymbolAddress((void**)&wt_p2, g_wt_p2);
    cudaGetSymbolAddress((void**)&wt_f2, g_wt_f2);

    cudaFuncSetAttribute(gemm_dual,
                         cudaFuncAttributeMaxDynamicSharedMemorySize,
                         2 * SM_BUF);

    init_kernel<<<256, 256>>>();
    convert_seq_kernel<<<BB * 512 / (256 * 8), 256>>>(seq, seq_h);

    transpose_kernel<<<dim3(16, 16), dim3(32, 8)>>>(pw1, wt_p1, 512);
    transpose_kernel<<<dim3(16, 16), dim3(32, 8)>>>(fw1, wt_f1, 512);
    transpose_kernel<<<dim3(8, 16), dim3(32, 8)>>>(pw2, wt_p2, 256);
    transpose_kernel<<<dim3(16, 16), dim3(32, 8)>>>(fw2, wt_f2, 512);

    // step-invariant base: seq @ W1[:512] + b1 (NO gelu); both branches fused
    gemm_dual<<<dim3(4, 128), 256, 2 * SM_BUF>>>(
        seq_h, wt_p1, pb1, base_p, 512, 2, 0,
        seq_h, wt_f1, fb1, base_f, 512, 0);

    for (int step = 0; step < 3; step++) {
        build_h1_kernel<<<BB / 8, 256>>>(pw1, fw1, perm_idx, step);
        // both per-step GEMMs in one launch: p (1 col block), f (2 col blocks)
        gemm_dual<<<dim3(3, 128), 256, 2 * SM_BUF>>>(
            h1_p, wt_p2, pb2, h2_p, 256, 1, 1,
            h1_f, wt_f2, fb2, h2_f, 512, 1);
        head_update_kernel<<<BB / 8, 256>>>(pw3, pb3, fw3, fb3, freq, pres,
                                            enrich, perm_idx, rmask, out, step);
    }

    finalize_kernel<<<1, 32>>>(out);
}

// round 6
// speedup vs baseline: 1.0892x; 1.0892x over previous
#include <cuda_runtime.h>
#include <cuda_fp16.h>
#include <math.h>
#include <stdint.h>

#define BB 16384
#define KK 512

// ---------------- scratch (device globals; no allocations) ----------------
__device__ __half g_seq_h[BB * 512];
__device__ __half g_base_p[BB * 512];
__device__ __half g_base_f[BB * 512];
__device__ __half g_h1_p[BB * 512];
__device__ __half g_h1_f[BB * 512];
__device__ __half g_h2_p[BB * 256];
__device__ __half g_h2_f[BB * 512];
__device__ __half g_wt_p1[512 * 512];   // pw1[0:512]^T  [n][k] fp16
__device__ __half g_wt_f1[512 * 512];   // fw1[0:512]^T
__device__ __half g_wt_p2[256 * 512];   // pw2^T
__device__ __half g_wt_f2[512 * 512];   // fw2^T
__device__ float g_pres_state[BB * 6];
__device__ float g_full_state[BB * 12];
__device__ float g_losses[4];  // lf, lp, le, nm

__constant__ int c_perms[6][3] = {
    {0, 1, 2}, {0, 2, 1}, {1, 0, 2}, {1, 2, 0}, {2, 0, 1}, {2, 1, 0}};

__device__ __forceinline__ float gelu_exact(float x) {
    return 0.5f * x * (1.0f + erff(x * 0.7071067811865475f));
}

// ================= PTX helpers (Ampere-era, safe on sm_103) ================
__device__ __forceinline__ uint32_t smem_u32(const void* p) {
    uint32_t a;
    asm("{ .reg .u64 t; cvta.to.shared.u64 t, %1; cvt.u32.u64 %0, t; }"
        : "=r"(a) : "l"(p));
    return a;
}
__device__ __forceinline__ void cp_async16(uint32_t dst, const void* src) {
    asm volatile("cp.async.ca.shared.global [%0], [%1], 16;" ::"r"(dst),
                 "l"(src) : "memory");
}
#define CP_COMMIT() asm volatile("cp.async.commit_group;" ::: "memory")
#define CP_WAIT(n) asm volatile("cp.async.wait_group %0;" ::"n"(n) : "memory")

__device__ __forceinline__ void ldsm_x4(uint32_t* r, uint32_t addr) {
    asm volatile(
        "ldmatrix.sync.aligned.m8n8.x4.shared.b16 {%0,%1,%2,%3}, [%4];"
        : "=r"(r[0]), "=r"(r[1]), "=r"(r[2]), "=r"(r[3])
        : "r"(addr));
}
__device__ __forceinline__ void mma_f16(float* c, const uint32_t* a,
                                        const uint32_t* b) {
    asm volatile(
        "mma.sync.aligned.m16n8k16.row.col.f32.f16.f16.f32 "
        "{%0,%1,%2,%3}, {%4,%5,%6,%7}, {%8,%9}, {%0,%1,%2,%3};"
        : "+f"(c[0]), "+f"(c[1]), "+f"(c[2]), "+f"(c[3])
        : "r"(a[0]), "r"(a[1]), "r"(a[2]), "r"(a[3]), "r"(b[0]), "r"(b[1]));
}

// ---------------- init ------------------------------------------------------
__global__ void init_kernel() {
    int i = blockIdx.x * blockDim.x + threadIdx.x;
    int stride = gridDim.x * blockDim.x;
    const int n = BB * 6 + BB * 12 + 4;
    for (; i < n; i += stride) {
        if (i < BB * 6) g_pres_state[i] = 0.f;
        else if (i < BB * 18) g_full_state[i - BB * 6] = 0.f;
        else g_losses[i - BB * 18] = 0.f;
    }
}

// ---------------- fp32 -> fp16 convert (seq_embed) --------------------------
__global__ void __launch_bounds__(256) convert_seq_kernel(
    const float* __restrict__ src, __half* __restrict__ dst) {
    const int i = (blockIdx.x * 256 + threadIdx.x) * 8;
    float4 v0 = *(const float4*)(src + i);
    float4 v1 = *(const float4*)(src + i + 4);
    __half2 h[4];
    h[0] = __floats2half2_rn(v0.x, v0.y);
    h[1] = __floats2half2_rn(v0.z, v0.w);
    h[2] = __floats2half2_rn(v1.x, v1.y);
    h[3] = __floats2half2_rn(v1.z, v1.w);
    *(uint4*)(dst + i) = *(uint4*)h;
}

// ---------------- weight transpose+convert: dst[n*512+k]=(half)src[k*N+n] ---
__global__ void transpose_kernel(const float* __restrict__ src,
                                 __half* __restrict__ dst, int N) {
    __shared__ float t[32][33];
    const int n0 = blockIdx.x * 32, k0 = blockIdx.y * 32;
#pragma unroll
    for (int i = 0; i < 4; i++)
        t[threadIdx.y + i * 8][threadIdx.x] =
            src[(k0 + threadIdx.y + i * 8) * N + n0 + threadIdx.x];
    __syncthreads();
#pragma unroll
    for (int i = 0; i < 4; i++)
        dst[(n0 + threadIdx.y + i * 8) * 512 + k0 + threadIdx.x] =
            __float2half_rn(t[threadIdx.x][threadIdx.y + i * 8]);
}

// ---------------- fp16 tensor-core GEMM, dual-problem, 3-stage pipeline -----
// Two independent GEMMs per grid (branch select on blockIdx.x).
// C[BB,N](fp16) = A[BB,512](fp16) @ Wt^T (Wt [N][512] fp16, K-major) + bias
// BM=128, BN=128, BK=32; 256 threads (8 warps, 2x4), warp tile 64x32.
// 3-stage cp.async; one __syncthreads per K-iter; 80B-padded rows.
#define STG 20480   // per stage: A 128*80 + B 128*80
__global__ void __launch_bounds__(256, 2) gemm_dual(
    const __half* __restrict__ Ap, const __half* __restrict__ Wtp,
    const float* __restrict__ biasp, __half* __restrict__ Cp, int Np,
    int nbp, int gelup,
    const __half* __restrict__ Af, const __half* __restrict__ Wtf,
    const float* __restrict__ biasf, __half* __restrict__ Cf, int Nf,
    int geluf)
{
    extern __shared__ __align__(16) unsigned char smraw[];
    const uint32_t sb = smem_u32(smraw);

    int bx = blockIdx.x;
    const __half* A;
    const __half* Wt;
    const float* bias;
    __half* C;
    int N, do_gelu;
    if (bx < nbp) {
        A = Ap; Wt = Wtp; bias = biasp; C = Cp; N = Np; do_gelu = gelup;
    } else {
        bx -= nbp;
        A = Af; Wt = Wtf; bias = biasf; C = Cf; N = Nf; do_gelu = geluf;
    }

    const int tid = threadIdx.x;
    const int lane = tid & 31;
    const int wid = tid >> 5;
    const int warp_m = wid >> 2;   // 0..1
    const int warp_n = wid & 3;    // 0..3
    const int brow = blockIdx.y * 128;
    const int bcol = bx * 128;

    const __half* Ab = A + (size_t)brow * 512;
    const __half* Bb = Wt + (size_t)bcol * 512;

    float acc[4][4][4];
#pragma unroll
    for (int i = 0; i < 4; i++)
#pragma unroll
        for (int j = 0; j < 4; j++)
#pragma unroll
            for (int k = 0; k < 4; k++) acc[i][j][k] = 0.f;

#define LOAD_TILE(cidx, stg)                                                  \
    do {                                                                      \
        const int kc = (cidx) * 32;                                           \
        const uint32_t base = sb + (stg) * STG;                               \
        _Pragma("unroll")                                                     \
        for (int i = 0; i < 2; i++) {                                         \
            const int lin = tid + i * 256;                                    \
            const int r = lin >> 2, ch = lin & 3;                             \
            cp_async16(base + r * 80 + ch * 16,                               \
                       Ab + (size_t)r * 512 + kc + ch * 8);                   \
            cp_async16(base + 10240 + r * 80 + ch * 16,                       \
                       Bb + (size_t)r * 512 + kc + ch * 8);                   \
        }                                                                     \
    } while (0)

    LOAD_TILE(0, 0);
    CP_COMMIT();
    LOAD_TILE(1, 1);
    CP_COMMIT();

    const uint32_t a_off =
        (uint32_t)(warp_m * 64 + (lane & 15)) * 80 + ((lane >> 4) << 4);
    const uint32_t b_off = 10240 +
        (uint32_t)(warp_n * 32 + ((lane >> 4) << 3) + (lane & 7)) * 80 +
        (((lane >> 3) & 1) << 4);

    int stg = 0;
#pragma unroll 1
    for (int c = 0; c < 16; c++) {
        if (c < 14) CP_WAIT(1); else CP_WAIT(0);
        __syncthreads();
        const uint32_t sbuf = sb + stg * STG;

#pragma unroll
        for (int ks = 0; ks < 2; ks++) {
            uint32_t a[4][4], b[4][2];
#pragma unroll
            for (int mf = 0; mf < 4; mf++)
                ldsm_x4(a[mf], sbuf + a_off + mf * (16 * 80) + ks * 32);
#pragma unroll
            for (int g = 0; g < 2; g++) {
                uint32_t r[4];
                ldsm_x4(r, sbuf + b_off + g * (16 * 80) + ks * 32);
                b[g * 2][0] = r[0]; b[g * 2][1] = r[1];
                b[g * 2 + 1][0] = r[2]; b[g * 2 + 1][1] = r[3];
            }
#pragma unroll
            for (int mf = 0; mf < 4; mf++)
#pragma unroll
                for (int nf = 0; nf < 4; nf++)
                    mma_f16(acc[mf][nf], a[mf], b[nf]);
        }

        if (c < 14) {
            const int nstg = (stg + 2 > 2) ? stg - 1 : stg + 2;
            LOAD_TILE(c + 2, nstg);
            CP_COMMIT();
        }
        stg = (stg + 1 > 2) ? 0 : stg + 1;
    }

    // epilogue
    const int erow = warp_m * 64 + (lane >> 2);
    const int ecol = warp_n * 32 + (lane & 3) * 2;
#pragma unroll
    for (int nf = 0; nf < 4; nf++) {
        const int col = bcol + ecol + nf * 8;
        const float2 bv = *(const float2*)(bias + col);
#pragma unroll
        for (int mf = 0; mf < 4; mf++) {
            float x0 = acc[mf][nf][0] + bv.x;
            float x1 = acc[mf][nf][1] + bv.y;
            float x2 = acc[mf][nf][2] + bv.x;
            float x3 = acc[mf][nf][3] + bv.y;
            if (do_gelu) {
                x0 = gelu_exact(x0); x1 = gelu_exact(x1);
                x2 = gelu_exact(x2); x3 = gelu_exact(x3);
            }
            const int r0 = brow + erow + mf * 16;
            *(__half2*)(C + (size_t)r0 * N + col) = __floats2half2_rn(x0, x1);
            *(__half2*)(C + (size_t)(r0 + 8) * N + col) =
                __floats2half2_rn(x2, x3);
        }
    }
}

// ---------------- build h1: smem-cached correction weights ------------------
__global__ void __launch_bounds__(256) build_h1_kernel(
    const float* __restrict__ pw1, const float* __restrict__ fw1,
    const int* __restrict__ perm_idx, int step)
{
    __shared__ float wc[24][512];
    const int tid = threadIdx.x;
#pragma unroll
    for (int i = 0; i < 12; i++) {
        const int lin = tid + i * 256;
        const int row = lin >> 7;
        const int c4 = (lin & 127) << 2;
        const float* src = (row < 9) ? (pw1 + (512 + row) * 512 + c4)
                                     : (fw1 + (512 + row - 9) * 512 + c4);
        *(float4*)&wc[row][c4] = *(const float4*)src;
    }
    __syncthreads();

    const int n0 = tid * 2;
#pragma unroll 1
    for (int r = 0; r < 8; r++) {
        const int b = blockIdx.x * 8 + r;
        const int ridx = c_perms[__ldg(&perm_idx[b])][step];
        float ps[6], fs[12];
#pragma unroll
        for (int j = 0; j < 6; j++) ps[j] = __ldg(&g_pres_state[b * 6 + j]);
#pragma unroll
        for (int j = 0; j < 12; j++) fs[j] = __ldg(&g_full_state[b * 12 + j]);

        float2 hp = __half22float2(*(const __half2*)&g_base_p[b * 512 + n0]);
#pragma unroll
        for (int j = 0; j < 6; j++) {
            const float2 w = *(const float2*)&wc[j][n0];
            hp.x = fmaf(ps[j], w.x, hp.x);
            hp.y = fmaf(ps[j], w.y, hp.y);
        }
        {
            const float2 w = *(const float2*)&wc[6 + ridx][n0];
            hp.x += w.x; hp.y += w.y;
        }
        hp.x = gelu_exact(hp.x); hp.y = gelu_exact(hp.y);
        *(__half2*)&g_h1_p[b * 512 + n0] = __floats2half2_rn(hp.x, hp.y);

        float2 hf = __half22float2(*(const __half2*)&g_base_f[b * 512 + n0]);
#pragma unroll
        for (int j = 0; j < 12; j++) {
            const float2 w = *(const float2*)&wc[9 + j][n0];
            hf.x = fmaf(fs[j], w.x, hf.x);
            hf.y = fmaf(fs[j], w.y, hf.y);
        }
        {
            const float2 w = *(const float2*)&wc[21 + ridx][n0];
            hf.x += w.x; hf.y += w.y;
        }
        hf.x = gelu_exact(hf.x); hf.y = gelu_exact(hf.y);
        *(__half2*)&g_h1_f[b * 512 + n0] = __floats2half2_rn(hf.x, hf.y);
    }
}

// ---------------- head (3rd layer dots) + losses + state update -------------
__global__ void __launch_bounds__(256) head_update_kernel(
    const float* __restrict__ pw3, const float* __restrict__ pb3,
    const float* __restrict__ fw3, const float* __restrict__ fb3,
    const float* __restrict__ freq, const float* __restrict__ pres,
    const float* __restrict__ enrich, const int* __restrict__ perm_idx,
    const int* __restrict__ round_mask, float* __restrict__ out, int step)
{
    __shared__ float blk[4];
    const int tid = threadIdx.x;
    const int lane = tid & 31;
    const int w = tid >> 5;
    if (tid < 4) blk[tid] = 0.f;
    __syncthreads();

    const int b = blockIdx.x * 8 + w;
    float pp = 0.f, pf = 0.f, pe = 0.f;
    const __half2* hp = (const __half2*)(g_h2_p + b * 256);
    const __half2* hf = (const __half2*)(g_h2_f + b * 512);

#pragma unroll
    for (int m = lane; m < 128; m += 32) {
        const float2 v = __half22float2(hp[m]);
        const float2 wv = *(const float2*)&pw3[2 * m];
        pp = fmaf(v.x, wv.x, pp);
        pp = fmaf(v.y, wv.y, pp);
    }
#pragma unroll
    for (int m = lane; m < 256; m += 32) {
        const float2 v = __half22float2(hf[m]);
        const float4 f3 = *(const float4*)&fw3[4 * m];
        pf = fmaf(v.x, f3.x, pf);
        pe = fmaf(v.x, f3.y, pe);
        pf = fmaf(v.y, f3.z, pf);
        pe = fmaf(v.y, f3.w, pe);
    }
#pragma unroll
    for (int o = 16; o > 0; o >>= 1) {
        pp += __shfl_xor_sync(0xffffffffu, pp, o);
        pf += __shfl_xor_sync(0xffffffffu, pf, o);
        pe += __shfl_xor_sync(0xffffffffu, pe, o);
    }

    if (lane == 0) {
        pp += pb3[0];
        pf += fb3[0];
        pe += fb3[1];
        const int ridx = c_perms[perm_idx[b]][step];
        const float m = (float)round_mask[b * 3 + ridx];
        const float gt_f = freq[b * 3 + ridx];
        const float gt_p = pres[b * 3 + ridx];
        const float gt_e = enrich[b * 3 + ridx];

        const float dlf = (pf - gt_f) * (pf - gt_f) * m;
        const float bce = fmaxf(pp, 0.f) - pp * gt_p + log1pf(expf(-fabsf(pp)));
        const float dlp = bce * m;
        const float dle = (pe - gt_e) * (pe - gt_e) * m;

        const bool msk = m > 0.5f;
        const float act_f = msk ? fminf(fmaxf(pf, -10.f), 10.f) : gt_f;
        const float act_p = msk ? (1.f / (1.f + expf(-pp))) : gt_p;
        const float act_e = msk ? fminf(fmaxf(pe, -100.f), 100.f) : gt_e;

        g_pres_state[b * 6 + 2 * ridx + 0] = act_p;
        g_pres_state[b * 6 + 2 * ridx + 1] = 1.f;
        g_full_state[b * 12 + 4 * ridx + 0] = act_f;
        g_full_state[b * 12 + 4 * ridx + 1] = act_p;
        g_full_state[b * 12 + 4 * ridx + 2] = act_e;
        g_full_state[b * 12 + 4 * ridx + 3] = 1.f;

        out[3 + b * 3 + ridx] = act_f;
        out[3 + 3 * BB + b * 3 + ridx] = act_p;
        out[3 + 6 * BB + b * 3 + ridx] = act_e;

        atomicAdd(&blk[0], dlf);
        atomicAdd(&blk[1], dlp);
        atomicAdd(&blk[2], dle);
        atomicAdd(&blk[3], m);
    }
    __syncthreads();
    if (tid < 4) atomicAdd(&g_losses[tid], blk[tid]);
}

__global__ void finalize_kernel(float* __restrict__ out) {
    if (threadIdx.x == 0 && blockIdx.x == 0) {
        const float nm = g_losses[3] + 1e-8f;
        out[0] = g_losses[0] / nm;
        out[1] = g_losses[1] / nm;
        out[2] = g_losses[2] / nm;
    }
}

// ---------------- launcher --------------------------------------------------
extern "C" void kernel_launch(void* const* d_in, const int* in_sizes, int n_in,
                              void* d_out, int out_size)
{
    const float* seq      = (const float*)d_in[0];
    const float* freq     = (const float*)d_in[1];
    const float* pres     = (const float*)d_in[2];
    const float* enrich   = (const float*)d_in[3];
    const float* pw1      = (const float*)d_in[4];
    const float* pb1      = (const float*)d_in[5];
    const float* pw2      = (const float*)d_in[6];
    const float* pb2      = (const float*)d_in[7];
    const float* pw3      = (const float*)d_in[8];
    const float* pb3      = (const float*)d_in[9];
    const float* fw1      = (const float*)d_in[10];
    const float* fb1      = (const float*)d_in[11];
    const float* fw2      = (const float*)d_in[12];
    const float* fb2      = (const float*)d_in[13];
    const float* fw3      = (const float*)d_in[14];
    const float* fb3      = (const float*)d_in[15];
    const int*   perm_idx = (const int*)d_in[16];
    const int*   rmask    = (const int*)d_in[17];
    float* out = (float*)d_out;

    __half *seq_h, *base_p, *base_f, *h1_p, *h1_f, *h2_p, *h2_f;
    __half *wt_p1, *wt_f1, *wt_p2, *wt_f2;
    cudaGetSymbolAddress((void**)&seq_h, g_seq_h);
    cudaGetSymbolAddress((void**)&base_p, g_base_p);
    cudaGetSymbolAddress((void**)&base_f, g_base_f);
    cudaGetSymbolAddress((void**)&h1_p, g_h1_p);
    cudaGetSymbolAddress((void**)&h1_f, g_h1_f);
    cudaGetSymbolAddress((void**)&h2_p, g_h2_p);
    cudaGetSymbolAddress((void**)&h2_f, g_h2_f);
    cudaGetSymbolAddress((void**)&wt_p1, g_wt_p1);
    cudaGetSymbolAddress((void**)&wt_f1, g_wt_f1);
    cudaGetSymbolAddress((void**)&wt_p2, g_wt_p2);
    cudaGetSymbolAddress((void**)&wt_f2, g_wt_f2);

    cudaFuncSetAttribute(gemm_dual,
                         cudaFuncAttributeMaxDynamicSharedMemorySize,
                         3 * STG);

    init_kernel<<<256, 256>>>();
    convert_seq_kernel<<<BB * 512 / (256 * 8), 256>>>(seq, seq_h);

    transpose_kernel<<<dim3(16, 16), dim3(32, 8)>>>(pw1, wt_p1, 512);
    transpose_kernel<<<dim3(16, 16), dim3(32, 8)>>>(fw1, wt_f1, 512);
    transpose_kernel<<<dim3(8, 16), dim3(32, 8)>>>(pw2, wt_p2, 256);
    transpose_kernel<<<dim3(16, 16), dim3(32, 8)>>>(fw2, wt_f2, 512);

    // step-invariant base: seq @ W1[:512] + b1 (NO gelu); both branches fused
    gemm_dual<<<dim3(8, 128), 256, 3 * STG>>>(
        seq_h, wt_p1, pb1, base_p, 512, 4, 0,
        seq_h, wt_f1, fb1, base_f, 512, 0);

    for (int step = 0; step < 3; step++) {
        build_h1_kernel<<<BB / 8, 256>>>(pw1, fw1, perm_idx, step);
        // per-step GEMMs fused: p (2 col blocks), f (4 col blocks)
        gemm_dual<<<dim3(6, 128), 256, 3 * STG>>>(
            h1_p, wt_p2, pb2, h2_p, 256, 2, 1,
            h1_f, wt_f2, fb2, h2_f, 512, 1);
        head_update_kernel<<<BB / 8, 256>>>(pw3, pb3, fw3, fb3, freq, pres,
                                            enrich, perm_idx, rmask, out, step);
    }

    finalize_kernel<<<1, 32>>>(out);
}

// round 7
// speedup vs baseline: 1.2290x; 1.1284x over previous
#include <cuda_runtime.h>
#include <cuda_fp16.h>
#include <math.h>
#include <stdint.h>

#define BB 16384
#define KK 512

// ---------------- scratch (device globals; no allocations) ----------------
__device__ __half g_seq_h[BB * 512];
__device__ __half g_base_p[BB * 512];
__device__ __half g_base_f[BB * 512];
__device__ __half g_h1_p[BB * 512];
__device__ __half g_h1_f[BB * 512];
__device__ __half g_wt_p1[512 * 512];   // pw1[0:512]^T  [n][k] fp16
__device__ __half g_wt_f1[512 * 512];   // fw1[0:512]^T
__device__ __half g_wt_p2[256 * 512];   // pw2^T
__device__ __half g_wt_f2[512 * 512];   // fw2^T
__device__ float g_part_p[2 * BB * 2];  // [colblk][row][2] (second unused)
__device__ float g_part_f[4 * BB * 2];  // [colblk][row][{pf,pe}]
__device__ float g_pres_state[BB * 6];
__device__ float g_full_state[BB * 12];
__device__ float g_losses[4];  // lf, lp, le, nm

__constant__ int c_perms[6][3] = {
    {0, 1, 2}, {0, 2, 1}, {1, 0, 2}, {1, 2, 0}, {2, 0, 1}, {2, 1, 0}};

__device__ __forceinline__ float gelu_exact(float x) {
    return 0.5f * x * (1.0f + erff(x * 0.7071067811865475f));
}

// ================= PTX helpers (Ampere-era, safe on sm_103) ================
__device__ __forceinline__ uint32_t smem_u32(const void* p) {
    uint32_t a;
    asm("{ .reg .u64 t; cvta.to.shared.u64 t, %1; cvt.u32.u64 %0, t; }"
        : "=r"(a) : "l"(p));
    return a;
}
__device__ __forceinline__ void cp_async16(uint32_t dst, const void* src) {
    asm volatile("cp.async.ca.shared.global [%0], [%1], 16;" ::"r"(dst),
                 "l"(src) : "memory");
}
#define CP_COMMIT() asm volatile("cp.async.commit_group;" ::: "memory")
#define CP_WAIT(n) asm volatile("cp.async.wait_group %0;" ::"n"(n) : "memory")

__device__ __forceinline__ void ldsm_x4(uint32_t* r, uint32_t addr) {
    asm volatile(
        "ldmatrix.sync.aligned.m8n8.x4.shared.b16 {%0,%1,%2,%3}, [%4];"
        : "=r"(r[0]), "=r"(r[1]), "=r"(r[2]), "=r"(r[3])
        : "r"(addr));
}
__device__ __forceinline__ void mma_f16(float* c, const uint32_t* a,
                                        const uint32_t* b) {
    asm volatile(
        "mma.sync.aligned.m16n8k16.row.col.f32.f16.f16.f32 "
        "{%0,%1,%2,%3}, {%4,%5,%6,%7}, {%8,%9}, {%0,%1,%2,%3};"
        : "+f"(c[0]), "+f"(c[1]), "+f"(c[2]), "+f"(c[3])
        : "r"(a[0]), "r"(a[1]), "r"(a[2]), "r"(a[3]), "r"(b[0]), "r"(b[1]));
}

// ---------------- convert seq (fp32->fp16) + init states/losses -------------
__global__ void __launch_bounds__(256) convert_init_kernel(
    const float* __restrict__ src, __half* __restrict__ dst) {
    const int i = (blockIdx.x * 256 + threadIdx.x) * 8;
    float4 v0 = *(const float4*)(src + i);
    float4 v1 = *(const float4*)(src + i + 4);
    __half2 h[4];
    h[0] = __floats2half2_rn(v0.x, v0.y);
    h[1] = __floats2half2_rn(v0.z, v0.w);
    h[2] = __floats2half2_rn(v1.x, v1.y);
    h[3] = __floats2half2_rn(v1.z, v1.w);
    *(uint4*)(dst + i) = *(uint4*)h;

    // fold in state zeroing: blocks 0..1151 cover 16384*18 floats
    const int idx = blockIdx.x * 256 + threadIdx.x;
    if (idx < BB * 6) g_pres_state[idx] = 0.f;
    else if (idx < BB * 18) g_full_state[idx - BB * 6] = 0.f;
    else if (idx < BB * 18 + 4) g_losses[idx - BB * 18] = 0.f;
}

// ---------------- all 4 weight transposes in one launch ----------------------
__global__ void transpose4_kernel(const float* __restrict__ pw1,
                                  const float* __restrict__ fw1,
                                  const float* __restrict__ pw2,
                                  const float* __restrict__ fw2) {
    __shared__ float t[32][33];
    const int z = blockIdx.z;
    const float* src;
    __half* dst;
    int N;
    if (z == 0) { src = pw1; dst = g_wt_p1; N = 512; }
    else if (z == 1) { src = fw1; dst = g_wt_f1; N = 512; }
    else if (z == 2) { src = pw2; dst = g_wt_p2; N = 256; }
    else { src = fw2; dst = g_wt_f2; N = 512; }
    if (blockIdx.x * 32 >= N) return;

    const int n0 = blockIdx.x * 32, k0 = blockIdx.y * 32;
#pragma unroll
    for (int i = 0; i < 4; i++)
        t[threadIdx.y + i * 8][threadIdx.x] =
            src[(k0 + threadIdx.y + i * 8) * N + n0 + threadIdx.x];
    __syncthreads();
#pragma unroll
    for (int i = 0; i < 4; i++)
        dst[(n0 + threadIdx.y + i * 8) * 512 + k0 + threadIdx.x] =
            __float2half_rn(t[threadIdx.x][threadIdx.y + i * 8]);
}

// ---------------- fp16 tensor-core GEMM, dual-problem, 3-stage pipeline -----
// Two independent GEMMs per grid (branch select on blockIdx.x).
// mode 0: store C fp16 (no gelu). mode 1: store C fp16 with gelu.
// mode 2: gelu + reduce against w3 (width 1: w3[col]).
// mode 3: gelu + reduce against w3 (width 2: w3[col][2]).
// BM=128, BN=128, BK=32; 256 threads (8 warps, 2x4), warp tile 64x32.
#define STG 20480   // per stage: A 128*80 + B 128*80
__global__ void __launch_bounds__(256, 2) gemm_dual(
    const __half* __restrict__ Ap, const __half* __restrict__ Wtp,
    const float* __restrict__ biasp, void* __restrict__ outp, int Np,
    int nbp, int modep, const float* __restrict__ w3p,
    const __half* __restrict__ Af, const __half* __restrict__ Wtf,
    const float* __restrict__ biasf, void* __restrict__ outf, int Nf,
    int modef, const float* __restrict__ w3f)
{
    extern __shared__ __align__(16) unsigned char smraw[];
    const uint32_t sb = smem_u32(smraw);

    int bx = blockIdx.x;
    const __half* A;
    const __half* Wt;
    const float* bias;
    const float* w3;
    void* outpt;
    int N, mode;
    if (bx < nbp) {
        A = Ap; Wt = Wtp; bias = biasp; outpt = outp; N = Np; mode = modep;
        w3 = w3p;
    } else {
        bx -= nbp;
        A = Af; Wt = Wtf; bias = biasf; outpt = outf; N = Nf; mode = modef;
        w3 = w3f;
    }

    const int tid = threadIdx.x;
    const int lane = tid & 31;
    const int wid = tid >> 5;
    const int warp_m = wid >> 2;   // 0..1
    const int warp_n = wid & 3;    // 0..3
    const int brow = blockIdx.y * 128;
    const int bcol = bx * 128;

    const __half* Ab = A + (size_t)brow * 512;
    const __half* Bb = Wt + (size_t)bcol * 512;

    float acc[4][4][4];
#pragma unroll
    for (int i = 0; i < 4; i++)
#pragma unroll
        for (int j = 0; j < 4; j++)
#pragma unroll
            for (int k = 0; k < 4; k++) acc[i][j][k] = 0.f;

#define LOAD_TILE(cidx, stg)                                                  \
    do {                                                                      \
        const int kc = (cidx) * 32;                                           \
        const uint32_t base = sb + (stg) * STG;                               \
        _Pragma("unroll")                                                     \
        for (int i = 0; i < 2; i++) {                                         \
            const int lin = tid + i * 256;                                    \
            const int r = lin >> 2, ch = lin & 3;                             \
            cp_async16(base + r * 80 + ch * 16,                               \
                       Ab + (size_t)r * 512 + kc + ch * 8);                   \
            cp_async16(base + 10240 + r * 80 + ch * 16,                       \
                       Bb + (size_t)r * 512 + kc + ch * 8);                   \
        }                                                                     \
    } while (0)

    LOAD_TILE(0, 0);
    CP_COMMIT();
    LOAD_TILE(1, 1);
    CP_COMMIT();

    const uint32_t a_off =
        (uint32_t)(warp_m * 64 + (lane & 15)) * 80 + ((lane >> 4) << 4);
    const uint32_t b_off = 10240 +
        (uint32_t)(warp_n * 32 + ((lane >> 4) << 3) + (lane & 7)) * 80 +
        (((lane >> 3) & 1) << 4);

    int stg = 0;
#pragma unroll 1
    for (int c = 0; c < 16; c++) {
        if (c < 14) CP_WAIT(1); else CP_WAIT(0);
        __syncthreads();
        const uint32_t sbuf = sb + stg * STG;

#pragma unroll
        for (int ks = 0; ks < 2; ks++) {
            uint32_t a[4][4], b[4][2];
#pragma unroll
            for (int mf = 0; mf < 4; mf++)
                ldsm_x4(a[mf], sbuf + a_off + mf * (16 * 80) + ks * 32);
#pragma unroll
            for (int g = 0; g < 2; g++) {
                uint32_t r[4];
                ldsm_x4(r, sbuf + b_off + g * (16 * 80) + ks * 32);
                b[g * 2][0] = r[0]; b[g * 2][1] = r[1];
                b[g * 2 + 1][0] = r[2]; b[g * 2 + 1][1] = r[3];
            }
#pragma unroll
            for (int mf = 0; mf < 4; mf++)
#pragma unroll
                for (int nf = 0; nf < 4; nf++)
                    mma_f16(acc[mf][nf], a[mf], b[nf]);
        }

        if (c < 14) {
            const int nstg = (stg + 2 > 2) ? stg - 1 : stg + 2;
            LOAD_TILE(c + 2, nstg);
            CP_COMMIT();
        }
        stg = (stg + 1 > 2) ? 0 : stg + 1;
    }

    const int erow = warp_m * 64 + (lane >> 2);
    const int ecol = warp_n * 32 + (lane & 3) * 2;

    if (mode < 2) {
        // store C fp16 (optional gelu)
        __half* C = (__half*)outpt;
#pragma unroll
        for (int nf = 0; nf < 4; nf++) {
            const int col = bcol + ecol + nf * 8;
            const float2 bv = *(const float2*)(bias + col);
#pragma unroll
            for (int mf = 0; mf < 4; mf++) {
                float x0 = acc[mf][nf][0] + bv.x;
                float x1 = acc[mf][nf][1] + bv.y;
                float x2 = acc[mf][nf][2] + bv.x;
                float x3 = acc[mf][nf][3] + bv.y;
                if (mode == 1) {
                    x0 = gelu_exact(x0); x1 = gelu_exact(x1);
                    x2 = gelu_exact(x2); x3 = gelu_exact(x3);
                }
                const int r0 = brow + erow + mf * 16;
                *(__half2*)(C + (size_t)r0 * N + col) =
                    __floats2half2_rn(x0, x1);
                *(__half2*)(C + (size_t)(r0 + 8) * N + col) =
                    __floats2half2_rn(x2, x3);
            }
        }
    } else {
        // gelu + layer-3 dot reduce: per-row partial (pa, pb) for this colblk
        float ps[4][2][2];
#pragma unroll
        for (int i = 0; i < 4; i++)
#pragma unroll
            for (int j = 0; j < 2; j++) { ps[i][j][0] = 0.f; ps[i][j][1] = 0.f; }

#pragma unroll
        for (int nf = 0; nf < 4; nf++) {
            const int col = bcol + ecol + nf * 8;
            const float2 bv = *(const float2*)(bias + col);
            float w3a0, w3b0, w3a1, w3b1;
            if (mode == 3) {
                const float4 w = __ldg((const float4*)(w3 + 2 * col));
                w3a0 = w.x; w3b0 = w.y; w3a1 = w.z; w3b1 = w.w;
            } else {
                const float2 w = __ldg((const float2*)(w3 + col));
                w3a0 = w.x; w3a1 = w.y; w3b0 = 0.f; w3b1 = 0.f;
            }
#pragma unroll
            for (int mf = 0; mf < 4; mf++) {
                const float x0 = gelu_exact(acc[mf][nf][0] + bv.x);
                const float x1 = gelu_exact(acc[mf][nf][1] + bv.y);
                const float x2 = gelu_exact(acc[mf][nf][2] + bv.x);
                const float x3 = gelu_exact(acc[mf][nf][3] + bv.y);
                ps[mf][0][0] += x0 * w3a0 + x1 * w3a1;
                ps[mf][0][1] += x0 * w3b0 + x1 * w3b1;
                ps[mf][1][0] += x2 * w3a0 + x3 * w3a1;
                ps[mf][1][1] += x2 * w3b0 + x3 * w3b1;
            }
        }
        // reduce across the 4 lanes of each quad (same rows, different cols)
#pragma unroll
        for (int mf = 0; mf < 4; mf++)
#pragma unroll
            for (int pr = 0; pr < 2; pr++)
#pragma unroll
                for (int v = 0; v < 2; v++) {
                    float s = ps[mf][pr][v];
                    s += __shfl_xor_sync(0xffffffffu, s, 1);
                    s += __shfl_xor_sync(0xffffffffu, s, 2);
                    ps[mf][pr][v] = s;
                }

        float* red = (float*)smraw;  // [warp_n][128 rows][2] = 4KB
        __syncthreads();             // tiles no longer needed
        if ((lane & 3) == 0) {
#pragma unroll
            for (int mf = 0; mf < 4; mf++)
#pragma unroll
                for (int pr = 0; pr < 2; pr++) {
                    const int rc = warp_m * 64 + mf * 16 + pr * 8 + (lane >> 2);
                    float2 v = {ps[mf][pr][0], ps[mf][pr][1]};
                    *(float2*)&red[(warp_n * 128 + rc) * 2] = v;
                }
        }
        __syncthreads();
        if (tid < 128) {
            float2 s = {0.f, 0.f};
#pragma unroll
            for (int wn = 0; wn < 4; wn++) {
                const float2 v = *(const float2*)&red[(wn * 128 + tid) * 2];
                s.x += v.x; s.y += v.y;
            }
            float* part = (float*)outpt;
            *(float2*)&part[((size_t)bx * BB + brow + tid) * 2] = s;
        }
    }
}

// ---------------- build h1: smem-cached correction weights ------------------
__global__ void __launch_bounds__(256) build_h1_kernel(
    const float* __restrict__ pw1, const float* __restrict__ fw1,
    const int* __restrict__ perm_idx, int step)
{
    __shared__ float wc[24][512];
    const int tid = threadIdx.x;
#pragma unroll
    for (int i = 0; i < 12; i++) {
        const int lin = tid + i * 256;
        const int row = lin >> 7;
        const int c4 = (lin & 127) << 2;
        const float* src = (row < 9) ? (pw1 + (512 + row) * 512 + c4)
                                     : (fw1 + (512 + row - 9) * 512 + c4);
        *(float4*)&wc[row][c4] = *(const float4*)src;
    }
    __syncthreads();

    const int n0 = tid * 2;
#pragma unroll 1
    for (int r = 0; r < 8; r++) {
        const int b = blockIdx.x * 8 + r;
        const int ridx = c_perms[__ldg(&perm_idx[b])][step];
        float ps[6], fs[12];
#pragma unroll
        for (int j = 0; j < 6; j++) ps[j] = __ldg(&g_pres_state[b * 6 + j]);
#pragma unroll
        for (int j = 0; j < 12; j++) fs[j] = __ldg(&g_full_state[b * 12 + j]);

        float2 hp = __half22float2(*(const __half2*)&g_base_p[b * 512 + n0]);
#pragma unroll
        for (int j = 0; j < 6; j++) {
            const float2 w = *(const float2*)&wc[j][n0];
            hp.x = fmaf(ps[j], w.x, hp.x);
            hp.y = fmaf(ps[j], w.y, hp.y);
        }
        {
            const float2 w = *(const float2*)&wc[6 + ridx][n0];
            hp.x += w.x; hp.y += w.y;
        }
        hp.x = gelu_exact(hp.x); hp.y = gelu_exact(hp.y);
        *(__half2*)&g_h1_p[b * 512 + n0] = __floats2half2_rn(hp.x, hp.y);

        float2 hf = __half22float2(*(const __half2*)&g_base_f[b * 512 + n0]);
#pragma unroll
        for (int j = 0; j < 12; j++) {
            const float2 w = *(const float2*)&wc[9 + j][n0];
            hf.x = fmaf(fs[j], w.x, hf.x);
            hf.y = fmaf(fs[j], w.y, hf.y);
        }
        {
            const float2 w = *(const float2*)&wc[21 + ridx][n0];
            hf.x += w.x; hf.y += w.y;
        }
        hf.x = gelu_exact(hf.x); hf.y = gelu_exact(hf.y);
        *(__half2*)&g_h1_f[b * 512 + n0] = __floats2half2_rn(hf.x, hf.y);
    }
}

// ---------------- head scalar: combine partials, losses, state update -------
__global__ void __launch_bounds__(256) head_scalar_kernel(
    const float* __restrict__ pb3, const float* __restrict__ fb3,
    const float* __restrict__ freq, const float* __restrict__ pres,
    const float* __restrict__ enrich, const int* __restrict__ perm_idx,
    const int* __restrict__ round_mask, float* __restrict__ out, int step)
{
    __shared__ float blk[4];
    const int tid = threadIdx.x;
    if (tid < 4) blk[tid] = 0.f;
    __syncthreads();

    const int b = blockIdx.x * 256 + tid;

    float pp = g_part_p[(size_t)b * 2] + g_part_p[((size_t)BB + b) * 2] +
               pb3[0];
    float pf = fb3[0], pe = fb3[1];
#pragma unroll
    for (int j = 0; j < 4; j++) {
        pf += g_part_f[((size_t)j * BB + b) * 2];
        pe += g_part_f[((size_t)j * BB + b) * 2 + 1];
    }

    const int ridx = c_perms[perm_idx[b]][step];
    const float m = (float)round_mask[b * 3 + ridx];
    const float gt_f = freq[b * 3 + ridx];
    const float gt_p = pres[b * 3 + ridx];
    const float gt_e = enrich[b * 3 + ridx];

    float dlf = (pf - gt_f) * (pf - gt_f) * m;
    const float bce = fmaxf(pp, 0.f) - pp * gt_p + log1pf(expf(-fabsf(pp)));
    float dlp = bce * m;
    float dle = (pe - gt_e) * (pe - gt_e) * m;
    float dm = m;

    const bool msk = m > 0.5f;
    const float act_f = msk ? fminf(fmaxf(pf, -10.f), 10.f) : gt_f;
    const float act_p = msk ? (1.f / (1.f + expf(-pp))) : gt_p;
    const float act_e = msk ? fminf(fmaxf(pe, -100.f), 100.f) : gt_e;

    g_pres_state[b * 6 + 2 * ridx + 0] = act_p;
    g_pres_state[b * 6 + 2 * ridx + 1] = 1.f;
    g_full_state[b * 12 + 4 * ridx + 0] = act_f;
    g_full_state[b * 12 + 4 * ridx + 1] = act_p;
    g_full_state[b * 12 + 4 * ridx + 2] = act_e;
    g_full_state[b * 12 + 4 * ridx + 3] = 1.f;

    out[3 + b * 3 + ridx] = act_f;
    out[3 + 3 * BB + b * 3 + ridx] = act_p;
    out[3 + 6 * BB + b * 3 + ridx] = act_e;

    // warp then block reduction of the four loss terms
#pragma unroll
    for (int o = 16; o > 0; o >>= 1) {
        dlf += __shfl_xor_sync(0xffffffffu, dlf, o);
        dlp += __shfl_xor_sync(0xffffffffu, dlp, o);
        dle += __shfl_xor_sync(0xffffffffu, dle, o);
        dm  += __shfl_xor_sync(0xffffffffu, dm, o);
    }
    if ((tid & 31) == 0) {
        atomicAdd(&blk[0], dlf);
        atomicAdd(&blk[1], dlp);
        atomicAdd(&blk[2], dle);
        atomicAdd(&blk[3], dm);
    }
    __syncthreads();
    if (tid < 4) atomicAdd(&g_losses[tid], blk[tid]);
}

__global__ void finalize_kernel(float* __restrict__ out) {
    if (threadIdx.x == 0 && blockIdx.x == 0) {
        const float nm = g_losses[3] + 1e-8f;
        out[0] = g_losses[0] / nm;
        out[1] = g_losses[1] / nm;
        out[2] = g_losses[2] / nm;
    }
}

// ---------------- launcher --------------------------------------------------
extern "C" void kernel_launch(void* const* d_in, const int* in_sizes, int n_in,
                              void* d_out, int out_size)
{
    const float* seq      = (const float*)d_in[0];
    const float* freq     = (const float*)d_in[1];
    const float* pres     = (const float*)d_in[2];
    const float* enrich   = (const float*)d_in[3];
    const float* pw1      = (const float*)d_in[4];
    const float* pb1      = (const float*)d_in[5];
    const float* pw2      = (const float*)d_in[6];
    const float* pb2      = (const float*)d_in[7];
    const float* pw3      = (const float*)d_in[8];
    const float* pb3      = (const float*)d_in[9];
    const float* fw1      = (const float*)d_in[10];
    const float* fb1      = (const float*)d_in[11];
    const float* fw2      = (const float*)d_in[12];
    const float* fb2      = (const float*)d_in[13];
    const float* fw3      = (const float*)d_in[14];
    const float* fb3      = (const float*)d_in[15];
    const int*   perm_idx = (const int*)d_in[16];
    const int*   rmask    = (const int*)d_in[17];
    float* out = (float*)d_out;

    __half *seq_h, *base_p, *base_f, *h1_p, *h1_f;
    __half *wt_p1, *wt_f1, *wt_p2, *wt_f2;
    float *part_p, *part_f;
    cudaGetSymbolAddress((void**)&seq_h, g_seq_h);
    cudaGetSymbolAddress((void**)&base_p, g_base_p);
    cudaGetSymbolAddress((void**)&base_f, g_base_f);
    cudaGetSymbolAddress((void**)&h1_p, g_h1_p);
    cudaGetSymbolAddress((void**)&h1_f, g_h1_f);
    cudaGetSymbolAddress((void**)&wt_p1, g_wt_p1);
    cudaGetSymbolAddress((void**)&wt_f1, g_wt_f1);
    cudaGetSymbolAddress((void**)&wt_p2, g_wt_p2);
    cudaGetSymbolAddress((void**)&wt_f2, g_wt_f2);
    cudaGetSymbolAddress((void**)&part_p, g_part_p);
    cudaGetSymbolAddress((void**)&part_f, g_part_f);

    cudaFuncSetAttribute(gemm_dual,
                         cudaFuncAttributeMaxDynamicSharedMemorySize,
                         3 * STG);

    convert_init_kernel<<<BB * 512 / (256 * 8), 256>>>(seq, seq_h);
    transpose4_kernel<<<dim3(16, 16, 4), dim3(32, 8)>>>(pw1, fw1, pw2, fw2);

    // step-invariant base: seq @ W1[:512] + b1 (NO gelu); both branches fused
    gemm_dual<<<dim3(8, 128), 256, 3 * STG>>>(
        seq_h, wt_p1, pb1, base_p, 512, 4, 0, nullptr,
        seq_h, wt_f1, fb1, base_f, 512, 0, nullptr);

    for (int step = 0; step < 3; step++) {
        build_h1_kernel<<<BB / 8, 256>>>(pw1, fw1, perm_idx, step);
        // per-step GEMMs fused + layer-3 dot folded into epilogue:
        // p: 2 col blocks, reduce width1 (pw3); f: 4 col blocks, width2 (fw3)
        gemm_dual<<<dim3(6, 128), 256, 3 * STG>>>(
            h1_p, wt_p2, pb2, part_p, 256, 2, 2, pw3,
            h1_f, wt_f2, fb2, part_f, 512, 3, fw3);
        head_scalar_kernel<<<BB / 256, 256>>>(pb3, fb3, freq, pres, enrich,
                                              perm_idx, rmask, out, step);
    }

    finalize_kernel<<<1, 32>>>(out);
}

// round 8
// speedup vs baseline: 1.3472x; 1.0962x over previous
#include <cuda_runtime.h>
#include <cuda_fp16.h>
#include <math.h>
#include <stdint.h>

#define BB 16384
#define KK 512

// ---------------- scratch (device globals; no allocations) ----------------
__device__ __half g_seq_h[BB * 512];
__device__ __half g_base_p[BB * 512];
__device__ __half g_base_f[BB * 512];
__device__ __half g_h1_p[BB * 512];
__device__ __half g_h1_f[BB * 512];
__device__ __half g_wt_p1[512 * 512];   // pw1[0:512]^T  [n][k] fp16
__device__ __half g_wt_f1[512 * 512];   // fw1[0:512]^T
__device__ __half g_wt_p2[256 * 512];   // pw2^T
__device__ __half g_wt_f2[512 * 512];   // fw2^T
__device__ __half g_wc_h[24 * 512];     // correction rows fp16: pw1[512..520], fw1[512..526]
__device__ float g_part_p[2 * BB * 2];  // [colblk][row][2] (second unused)
__device__ float g_part_f[4 * BB * 2];  // [colblk][row][{pf,pe}]
__device__ float g_pres_state[BB * 6];
__device__ float g_full_state[BB * 12];
__device__ float g_losses[4];  // lf, lp, le, nm

__constant__ int c_perms[6][3] = {
    {0, 1, 2}, {0, 2, 1}, {1, 0, 2}, {1, 2, 0}, {2, 0, 1}, {2, 1, 0}};

__device__ __forceinline__ float gelu_exact(float x) {
    return 0.5f * x * (1.0f + erff(x * 0.7071067811865475f));
}

// ================= PTX helpers (Ampere-era, safe on sm_103) ================
__device__ __forceinline__ uint32_t smem_u32(const void* p) {
    uint32_t a;
    asm("{ .reg .u64 t; cvta.to.shared.u64 t, %1; cvt.u32.u64 %0, t; }"
        : "=r"(a) : "l"(p));
    return a;
}
__device__ __forceinline__ void cp_async16(uint32_t dst, const void* src) {
    asm volatile("cp.async.ca.shared.global [%0], [%1], 16;" ::"r"(dst),
                 "l"(src) : "memory");
}
#define CP_COMMIT() asm volatile("cp.async.commit_group;" ::: "memory")
#define CP_WAIT(n) asm volatile("cp.async.wait_group %0;" ::"n"(n) : "memory")

__device__ __forceinline__ void ldsm_x4(uint32_t* r, uint32_t addr) {
    asm volatile(
        "ldmatrix.sync.aligned.m8n8.x4.shared.b16 {%0,%1,%2,%3}, [%4];"
        : "=r"(r[0]), "=r"(r[1]), "=r"(r[2]), "=r"(r[3])
        : "r"(addr));
}
__device__ __forceinline__ void mma_f16(float* c, const uint32_t* a,
                                        const uint32_t* b) {
    asm volatile(
        "mma.sync.aligned.m16n8k16.row.col.f32.f16.f16.f32 "
        "{%0,%1,%2,%3}, {%4,%5,%6,%7}, {%8,%9}, {%0,%1,%2,%3};"
        : "+f"(c[0]), "+f"(c[1]), "+f"(c[2]), "+f"(c[3])
        : "r"(a[0]), "r"(a[1]), "r"(a[2]), "r"(a[3]), "r"(b[0]), "r"(b[1]));
}

// ---------------- convert seq (fp32->fp16) + init states/losses -------------
__global__ void __launch_bounds__(256) convert_init_kernel(
    const float* __restrict__ src, __half* __restrict__ dst) {
    const int i = (blockIdx.x * 256 + threadIdx.x) * 8;
    float4 v0 = *(const float4*)(src + i);
    float4 v1 = *(const float4*)(src + i + 4);
    __half2 h[4];
    h[0] = __floats2half2_rn(v0.x, v0.y);
    h[1] = __floats2half2_rn(v0.z, v0.w);
    h[2] = __floats2half2_rn(v1.x, v1.y);
    h[3] = __floats2half2_rn(v1.z, v1.w);
    *(uint4*)(dst + i) = *(uint4*)h;

    const int idx = blockIdx.x * 256 + threadIdx.x;
    if (idx < BB * 6) g_pres_state[idx] = 0.f;
    else if (idx < BB * 18) g_full_state[idx - BB * 6] = 0.f;
    else if (idx < BB * 18 + 4) g_losses[idx - BB * 18] = 0.f;
}

// ------ all 4 weight transposes + correction-row fp16 convert in one launch --
__global__ void transpose4_kernel(const float* __restrict__ pw1,
                                  const float* __restrict__ fw1,
                                  const float* __restrict__ pw2,
                                  const float* __restrict__ fw2) {
    __shared__ float t[32][33];
    const int z = blockIdx.z;
    if (z == 4) {
        // correction rows -> g_wc_h[24][512] fp16
        const int row = blockIdx.y * 8 + threadIdx.y;
        if (row >= 24) return;
        const int col = blockIdx.x * 32 + threadIdx.x;
        const float* src = (row < 9) ? (pw1 + (512 + row) * 512)
                                     : (fw1 + (512 + row - 9) * 512);
        g_wc_h[row * 512 + col] = __float2half_rn(src[col]);
        return;
    }
    const float* src;
    __half* dst;
    int N;
    if (z == 0) { src = pw1; dst = g_wt_p1; N = 512; }
    else if (z == 1) { src = fw1; dst = g_wt_f1; N = 512; }
    else if (z == 2) { src = pw2; dst = g_wt_p2; N = 256; }
    else { src = fw2; dst = g_wt_f2; N = 512; }
    if (blockIdx.x * 32 >= N) return;

    const int n0 = blockIdx.x * 32, k0 = blockIdx.y * 32;
#pragma unroll
    for (int i = 0; i < 4; i++)
        t[threadIdx.y + i * 8][threadIdx.x] =
            src[(k0 + threadIdx.y + i * 8) * N + n0 + threadIdx.x];
    __syncthreads();
#pragma unroll
    for (int i = 0; i < 4; i++)
        dst[(n0 + threadIdx.y + i * 8) * 512 + k0 + threadIdx.x] =
            __float2half_rn(t[threadIdx.x][threadIdx.y + i * 8]);
}

// ---------------- fp16 tensor-core GEMM, dual-problem, 3-stage pipeline -----
// Two independent GEMMs per grid (branch select on blockIdx.x).
// mode 0: store C fp16 (no gelu). mode 1: store C fp16 with gelu.
// mode 2: gelu + reduce against w3 (width 1). mode 3: gelu + reduce width 2.
#define STG 20480   // per stage: A 128*80 + B 128*80
__global__ void __launch_bounds__(256, 2) gemm_dual(
    const __half* __restrict__ Ap, const __half* __restrict__ Wtp,
    const float* __restrict__ biasp, void* __restrict__ outp, int Np,
    int nbp, int modep, const float* __restrict__ w3p,
    const __half* __restrict__ Af, const __half* __restrict__ Wtf,
    const float* __restrict__ biasf, void* __restrict__ outf, int Nf,
    int modef, const float* __restrict__ w3f)
{
    extern __shared__ __align__(16) unsigned char smraw[];
    const uint32_t sb = smem_u32(smraw);

    int bx = blockIdx.x;
    const __half* A;
    const __half* Wt;
    const float* bias;
    const float* w3;
    void* outpt;
    int N, mode;
    if (bx < nbp) {
        A = Ap; Wt = Wtp; bias = biasp; outpt = outp; N = Np; mode = modep;
        w3 = w3p;
    } else {
        bx -= nbp;
        A = Af; Wt = Wtf; bias = biasf; outpt = outf; N = Nf; mode = modef;
        w3 = w3f;
    }

    const int tid = threadIdx.x;
    const int lane = tid & 31;
    const int wid = tid >> 5;
    const int warp_m = wid >> 2;   // 0..1
    const int warp_n = wid & 3;    // 0..3
    const int brow = blockIdx.y * 128;
    const int bcol = bx * 128;

    const __half* Ab = A + (size_t)brow * 512;
    const __half* Bb = Wt + (size_t)bcol * 512;

    float acc[4][4][4];
#pragma unroll
    for (int i = 0; i < 4; i++)
#pragma unroll
        for (int j = 0; j < 4; j++)
#pragma unroll
            for (int k = 0; k < 4; k++) acc[i][j][k] = 0.f;

#define LOAD_TILE(cidx, stg)                                                  \
    do {                                                                      \
        const int kc = (cidx) * 32;                                           \
        const uint32_t base = sb + (stg) * STG;                               \
        _Pragma("unroll")                                                     \
        for (int i = 0; i < 2; i++) {                                         \
            const int lin = tid + i * 256;                                    \
            const int r = lin >> 2, ch = lin & 3;                             \
            cp_async16(base + r * 80 + ch * 16,                               \
                       Ab + (size_t)r * 512 + kc + ch * 8);                   \
            cp_async16(base + 10240 + r * 80 + ch * 16,                       \
                       Bb + (size_t)r * 512 + kc + ch * 8);                   \
        }                                                                     \
    } while (0)

    LOAD_TILE(0, 0);
    CP_COMMIT();
    LOAD_TILE(1, 1);
    CP_COMMIT();

    const uint32_t a_off =
        (uint32_t)(warp_m * 64 + (lane & 15)) * 80 + ((lane >> 4) << 4);
    const uint32_t b_off = 10240 +
        (uint32_t)(warp_n * 32 + ((lane >> 4) << 3) + (lane & 7)) * 80 +
        (((lane >> 3) & 1) << 4);

    int stg = 0;
#pragma unroll 1
    for (int c = 0; c < 16; c++) {
        if (c < 14) CP_WAIT(1); else CP_WAIT(0);
        __syncthreads();
        const uint32_t sbuf = sb + stg * STG;

#pragma unroll
        for (int ks = 0; ks < 2; ks++) {
            uint32_t a[4][4], b[4][2];
#pragma unroll
            for (int mf = 0; mf < 4; mf++)
                ldsm_x4(a[mf], sbuf + a_off + mf * (16 * 80) + ks * 32);
#pragma unroll
            for (int g = 0; g < 2; g++) {
                uint32_t r[4];
                ldsm_x4(r, sbuf + b_off + g * (16 * 80) + ks * 32);
                b[g * 2][0] = r[0]; b[g * 2][1] = r[1];
                b[g * 2 + 1][0] = r[2]; b[g * 2 + 1][1] = r[3];
            }
#pragma unroll
            for (int mf = 0; mf < 4; mf++)
#pragma unroll
                for (int nf = 0; nf < 4; nf++)
                    mma_f16(acc[mf][nf], a[mf], b[nf]);
        }

        if (c < 14) {
            const int nstg = (stg + 2 > 2) ? stg - 1 : stg + 2;
            LOAD_TILE(c + 2, nstg);
            CP_COMMIT();
        }
        stg = (stg + 1 > 2) ? 0 : stg + 1;
    }

    const int erow = warp_m * 64 + (lane >> 2);
    const int ecol = warp_n * 32 + (lane & 3) * 2;

    if (mode < 2) {
        __half* C = (__half*)outpt;
#pragma unroll
        for (int nf = 0; nf < 4; nf++) {
            const int col = bcol + ecol + nf * 8;
            const float2 bv = *(const float2*)(bias + col);
#pragma unroll
            for (int mf = 0; mf < 4; mf++) {
                float x0 = acc[mf][nf][0] + bv.x;
                float x1 = acc[mf][nf][1] + bv.y;
                float x2 = acc[mf][nf][2] + bv.x;
                float x3 = acc[mf][nf][3] + bv.y;
                if (mode == 1) {
                    x0 = gelu_exact(x0); x1 = gelu_exact(x1);
                    x2 = gelu_exact(x2); x3 = gelu_exact(x3);
                }
                const int r0 = brow + erow + mf * 16;
                *(__half2*)(C + (size_t)r0 * N + col) =
                    __floats2half2_rn(x0, x1);
                *(__half2*)(C + (size_t)(r0 + 8) * N + col) =
                    __floats2half2_rn(x2, x3);
            }
        }
    } else {
        // gelu + layer-3 dot reduce
        float ps[4][2][2];
#pragma unroll
        for (int i = 0; i < 4; i++)
#pragma unroll
            for (int j = 0; j < 2; j++) { ps[i][j][0] = 0.f; ps[i][j][1] = 0.f; }

#pragma unroll
        for (int nf = 0; nf < 4; nf++) {
            const int col = bcol + ecol + nf * 8;
            const float2 bv = *(const float2*)(bias + col);
            float w3a0, w3b0, w3a1, w3b1;
            if (mode == 3) {
                const float4 w = __ldg((const float4*)(w3 + 2 * col));
                w3a0 = w.x; w3b0 = w.y; w3a1 = w.z; w3b1 = w.w;
            } else {
                const float2 w = __ldg((const float2*)(w3 + col));
                w3a0 = w.x; w3a1 = w.y; w3b0 = 0.f; w3b1 = 0.f;
            }
#pragma unroll
            for (int mf = 0; mf < 4; mf++) {
                const float x0 = gelu_exact(acc[mf][nf][0] + bv.x);
                const float x1 = gelu_exact(acc[mf][nf][1] + bv.y);
                const float x2 = gelu_exact(acc[mf][nf][2] + bv.x);
                const float x3 = gelu_exact(acc[mf][nf][3] + bv.y);
                ps[mf][0][0] += x0 * w3a0 + x1 * w3a1;
                ps[mf][0][1] += x0 * w3b0 + x1 * w3b1;
                ps[mf][1][0] += x2 * w3a0 + x3 * w3a1;
                ps[mf][1][1] += x2 * w3b0 + x3 * w3b1;
            }
        }
#pragma unroll
        for (int mf = 0; mf < 4; mf++)
#pragma unroll
            for (int pr = 0; pr < 2; pr++)
#pragma unroll
                for (int v = 0; v < 2; v++) {
                    float s = ps[mf][pr][v];
                    s += __shfl_xor_sync(0xffffffffu, s, 1);
                    s += __shfl_xor_sync(0xffffffffu, s, 2);
                    ps[mf][pr][v] = s;
                }

        float* red = (float*)smraw;
        __syncthreads();
        if ((lane & 3) == 0) {
#pragma unroll
            for (int mf = 0; mf < 4; mf++)
#pragma unroll
                for (int pr = 0; pr < 2; pr++) {
                    const int rc = warp_m * 64 + mf * 16 + pr * 8 + (lane >> 2);
                    float2 v = {ps[mf][pr][0], ps[mf][pr][1]};
                    *(float2*)&red[(warp_n * 128 + rc) * 2] = v;
                }
        }
        __syncthreads();
        if (tid < 128) {
            float2 s = {0.f, 0.f};
#pragma unroll
            for (int wn = 0; wn < 4; wn++) {
                const float2 v = *(const float2*)&red[(wn * 128 + tid) * 2];
                s.x += v.x; s.y += v.y;
            }
            float* part = (float*)outpt;
            *(float2*)&part[((size_t)bx * BB + brow + tid) * 2] = s;
        }
    }
}

// ---------------- build h1 v3: coalesced fp16 weight loads, 2 rows/block ----
__global__ void __launch_bounds__(256) build_h1_kernel(
    const int* __restrict__ perm_idx, int step)
{
    const int tid = threadIdx.x;
    const int rh = tid >> 7;            // 0..1: which row of this block
    const int lt = tid & 127;
    const int b = blockIdx.x * 2 + rh;
    const int n0 = lt * 4;
    const int ridx = c_perms[__ldg(&perm_idx[b])][step];

    float ps[6], fs[12];
#pragma unroll
    for (int j = 0; j < 6; j++) ps[j] = __ldg(&g_pres_state[b * 6 + j]);
#pragma unroll
    for (int j = 0; j < 12; j++) fs[j] = __ldg(&g_full_state[b * 12 + j]);

    // ---- pres branch: wc rows 0..5 state, 6+ridx onehot ----
    float a0, a1, a2, a3;
    {
        const uint2 braw = *(const uint2*)&g_base_p[b * 512 + n0];
        const float2 b01 = __half22float2(*(const __half2*)&braw.x);
        const float2 b23 = __half22float2(*(const __half2*)&braw.y);
        a0 = b01.x; a1 = b01.y; a2 = b23.x; a3 = b23.y;
    }
#pragma unroll
    for (int j = 0; j < 6; j++) {
        const uint2 w = __ldg((const uint2*)&g_wc_h[j * 512 + n0]);
        const float2 w01 = __half22float2(*(const __half2*)&w.x);
        const float2 w23 = __half22float2(*(const __half2*)&w.y);
        a0 = fmaf(ps[j], w01.x, a0); a1 = fmaf(ps[j], w01.y, a1);
        a2 = fmaf(ps[j], w23.x, a2); a3 = fmaf(ps[j], w23.y, a3);
    }
    {
        const uint2 w = __ldg((const uint2*)&g_wc_h[(6 + ridx) * 512 + n0]);
        const float2 w01 = __half22float2(*(const __half2*)&w.x);
        const float2 w23 = __half22float2(*(const __half2*)&w.y);
        a0 += w01.x; a1 += w01.y; a2 += w23.x; a3 += w23.y;
    }
    {
        __half2 o01 = __floats2half2_rn(gelu_exact(a0), gelu_exact(a1));
        __half2 o23 = __floats2half2_rn(gelu_exact(a2), gelu_exact(a3));
        uint2 o;
        o.x = *(uint32_t*)&o01; o.y = *(uint32_t*)&o23;
        *(uint2*)&g_h1_p[b * 512 + n0] = o;
    }

    // ---- full branch: wc rows 9..20 state, 21+ridx onehot ----
    {
        const uint2 braw = *(const uint2*)&g_base_f[b * 512 + n0];
        const float2 b01 = __half22float2(*(const __half2*)&braw.x);
        const float2 b23 = __half22float2(*(const __half2*)&braw.y);
        a0 = b01.x; a1 = b01.y; a2 = b23.x; a3 = b23.y;
    }
#pragma unroll
    for (int j = 0; j < 12; j++) {
        const uint2 w = __ldg((const uint2*)&g_wc_h[(9 + j) * 512 + n0]);
        const float2 w01 = __half22float2(*(const __half2*)&w.x);
        const float2 w23 = __half22float2(*(const __half2*)&w.y);
        a0 = fmaf(fs[j], w01.x, a0); a1 = fmaf(fs[j], w01.y, a1);
        a2 = fmaf(fs[j], w23.x, a2); a3 = fmaf(fs[j], w23.y, a3);
    }
    {
        const uint2 w = __ldg((const uint2*)&g_wc_h[(21 + ridx) * 512 + n0]);
        const float2 w01 = __half22float2(*(const __half2*)&w.x);
        const float2 w23 = __half22float2(*(const __half2*)&w.y);
        a0 += w01.x; a1 += w01.y; a2 += w23.x; a3 += w23.y;
    }
    {
        __half2 o01 = __floats2half2_rn(gelu_exact(a0), gelu_exact(a1));
        __half2 o23 = __floats2half2_rn(gelu_exact(a2), gelu_exact(a3));
        uint2 o;
        o.x = *(uint32_t*)&o01; o.y = *(uint32_t*)&o23;
        *(uint2*)&g_h1_f[b * 512 + n0] = o;
    }
}

// ---------------- head scalar: combine partials, losses, state update -------
__global__ void __launch_bounds__(256) head_scalar_kernel(
    const float* __restrict__ pb3, const float* __restrict__ fb3,
    const float* __restrict__ freq, const float* __restrict__ pres,
    const float* __restrict__ enrich, const int* __restrict__ perm_idx,
    const int* __restrict__ round_mask, float* __restrict__ out, int step)
{
    __shared__ float blk[4];
    const int tid = threadIdx.x;
    if (tid < 4) blk[tid] = 0.f;
    __syncthreads();

    const int b = blockIdx.x * 256 + tid;

    float pp = g_part_p[(size_t)b * 2] + g_part_p[((size_t)BB + b) * 2] +
               pb3[0];
    float pf = fb3[0], pe = fb3[1];
#pragma unroll
    for (int j = 0; j < 4; j++) {
        pf += g_part_f[((size_t)j * BB + b) * 2];
        pe += g_part_f[((size_t)j * BB + b) * 2 + 1];
    }

    const int ridx = c_perms[perm_idx[b]][step];
    const float m = (float)round_mask[b * 3 + ridx];
    const float gt_f = freq[b * 3 + ridx];
    const float gt_p = pres[b * 3 + ridx];
    const float gt_e = enrich[b * 3 + ridx];

    float dlf = (pf - gt_f) * (pf - gt_f) * m;
    const float bce = fmaxf(pp, 0.f) - pp * gt_p + log1pf(expf(-fabsf(pp)));
    float dlp = bce * m;
    float dle = (pe - gt_e) * (pe - gt_e) * m;
    float dm = m;

    const bool msk = m > 0.5f;
    const float act_f = msk ? fminf(fmaxf(pf, -10.f), 10.f) : gt_f;
    const float act_p = msk ? (1.f / (1.f + expf(-pp))) : gt_p;
    const float act_e = msk ? fminf(fmaxf(pe, -100.f), 100.f) : gt_e;

    g_pres_state[b * 6 + 2 * ridx + 0] = act_p;
    g_pres_state[b * 6 + 2 * ridx + 1] = 1.f;
    g_full_state[b * 12 + 4 * ridx + 0] = act_f;
    g_full_state[b * 12 + 4 * ridx + 1] = act_p;
    g_full_state[b * 12 + 4 * ridx + 2] = act_e;
    g_full_state[b * 12 + 4 * ridx + 3] = 1.f;

    out[3 + b * 3 + ridx] = act_f;
    out[3 + 3 * BB + b * 3 + ridx] = act_p;
    out[3 + 6 * BB + b * 3 + ridx] = act_e;

#pragma unroll
    for (int o = 16; o > 0; o >>= 1) {
        dlf += __shfl_xor_sync(0xffffffffu, dlf, o);
        dlp += __shfl_xor_sync(0xffffffffu, dlp, o);
        dle += __shfl_xor_sync(0xffffffffu, dle, o);
        dm  += __shfl_xor_sync(0xffffffffu, dm, o);
    }
    if ((tid & 31) == 0) {
        atomicAdd(&blk[0], dlf);
        atomicAdd(&blk[1], dlp);
        atomicAdd(&blk[2], dle);
        atomicAdd(&blk[3], dm);
    }
    __syncthreads();
    if (tid < 4) atomicAdd(&g_losses[tid], blk[tid]);
}

__global__ void finalize_kernel(float* __restrict__ out) {
    if (threadIdx.x == 0 && blockIdx.x == 0) {
        const float nm = g_losses[3] + 1e-8f;
        out[0] = g_losses[0] / nm;
        out[1] = g_losses[1] / nm;
        out[2] = g_losses[2] / nm;
    }
}

// ---------------- launcher --------------------------------------------------
extern "C" void kernel_launch(void* const* d_in, const int* in_sizes, int n_in,
                              void* d_out, int out_size)
{
    const float* seq      = (const float*)d_in[0];
    const float* freq     = (const float*)d_in[1];
    const float* pres     = (const float*)d_in[2];
    const float* enrich   = (const float*)d_in[3];
    const float* pw1      = (const float*)d_in[4];
    const float* pb1      = (const float*)d_in[5];
    const float* pw2      = (const float*)d_in[6];
    const float* pb2      = (const float*)d_in[7];
    const float* pw3      = (const float*)d_in[8];
    const float* pb3      = (const float*)d_in[9];
    const float* fw1      = (const float*)d_in[10];
    const float* fb1      = (const float*)d_in[11];
    const float* fw2      = (const float*)d_in[12];
    const float* fb2      = (const float*)d_in[13];
    const float* fw3      = (const float*)d_in[14];
    const float* fb3      = (const float*)d_in[15];
    const int*   perm_idx = (const int*)d_in[16];
    const int*   rmask    = (const int*)d_in[17];
    float* out = (float*)d_out;

    __half *seq_h, *base_p, *base_f, *h1_p, *h1_f;
    __half *wt_p1, *wt_f1, *wt_p2, *wt_f2;
    float *part_p, *part_f;
    cudaGetSymbolAddress((void**)&seq_h, g_seq_h);
    cudaGetSymbolAddress((void**)&base_p, g_base_p);
    cudaGetSymbolAddress((void**)&base_f, g_base_f);
    cudaGetSymbolAddress((void**)&h1_p, g_h1_p);
    cudaGetSymbolAddress((void**)&h1_f, g_h1_f);
    cudaGetSymbolAddress((void**)&wt_p1, g_wt_p1);
    cudaGetSymbolAddress((void**)&wt_f1, g_wt_f1);
    cudaGetSymbolAddress((void**)&wt_p2, g_wt_p2);
    cudaGetSymbolAddress((void**)&wt_f2, g_wt_f2);
    cudaGetSymbolAddress((void**)&part_p, g_part_p);
    cudaGetSymbolAddress((void**)&part_f, g_part_f);

    cudaFuncSetAttribute(gemm_dual,
                         cudaFuncAttributeMaxDynamicSharedMemorySize,
                         3 * STG);

    convert_init_kernel<<<BB * 512 / (256 * 8), 256>>>(seq, seq_h);
    transpose4_kernel<<<dim3(16, 16, 5), dim3(32, 8)>>>(pw1, fw1, pw2, fw2);

    // step-invariant base: seq @ W1[:512] + b1 (NO gelu); both branches fused
    gemm_dual<<<dim3(8, 128), 256, 3 * STG>>>(
        seq_h, wt_p1, pb1, base_p, 512, 4, 0, nullptr,
        seq_h, wt_f1, fb1, base_f, 512, 0, nullptr);

    for (int step = 0; step < 3; step++) {
        build_h1_kernel<<<BB / 2, 256>>>(perm_idx, step);
        // per-step GEMMs fused + layer-3 dot folded into epilogue
        gemm_dual<<<dim3(6, 128), 256, 3 * STG>>>(
            h1_p, wt_p2, pb2, part_p, 256, 2, 2, pw3,
            h1_f, wt_f2, fb2, part_f, 512, 3, fw3);
        head_scalar_kernel<<<BB / 256, 256>>>(pb3, fb3, freq, pres, enrich,
                                              perm_idx, rmask, out, step);
    }

    finalize_kernel<<<1, 32>>>(out);
}

// round 9
// speedup vs baseline: 1.4265x; 1.0589x over previous
#include <cuda_runtime.h>
#include <cuda_fp16.h>
#include <math.h>
#include <stdint.h>

#define BB 16384
#define KK 512

// ---------------- scratch (device globals; no allocations) ----------------
__device__ __half g_seq_h[BB * 512];
__device__ __half g_base_p[BB * 512];
__device__ __half g_base_f[BB * 512];
__device__ __half g_h1_p[BB * 512];
__device__ __half g_h1_f[BB * 512];
__device__ __half g_wt_p1[512 * 512];   // pw1[0:512]^T  [n][k] fp16
__device__ __half g_wt_f1[512 * 512];   // fw1[0:512]^T
__device__ __half g_wt_p2[256 * 512];   // pw2^T
__device__ __half g_wt_f2[512 * 512];   // fw2^T
__device__ __half g_wc_h[24 * 512];     // fp16 correction rows: pw1[512..520], fw1[512..526]
__device__ float g_part_p[2 * BB * 2];  // [colblk][row][2] (second unused)
__device__ float g_part_f[4 * BB * 2];  // [colblk][row][{pf,pe}]
__device__ float g_full_state[BB * 12]; // slot r: {act_f, act_p, act_e, 1}
__device__ float g_losses[4];           // lf, lp, le, nm

__constant__ int c_perms[6][3] = {
    {0, 1, 2}, {0, 2, 1}, {1, 0, 2}, {1, 2, 0}, {2, 0, 1}, {2, 1, 0}};

__device__ __forceinline__ float gelu_exact(float x) {
    return 0.5f * x * (1.0f + erff(x * 0.7071067811865475f));
}

// ================= PTX helpers (Ampere-era, safe on sm_103) ================
__device__ __forceinline__ uint32_t smem_u32(const void* p) {
    uint32_t a;
    asm("{ .reg .u64 t; cvta.to.shared.u64 t, %1; cvt.u32.u64 %0, t; }"
        : "=r"(a) : "l"(p));
    return a;
}
__device__ __forceinline__ void cp_async16(uint32_t dst, const void* src) {
    asm volatile("cp.async.ca.shared.global [%0], [%1], 16;" ::"r"(dst),
                 "l"(src) : "memory");
}
#define CP_COMMIT() asm volatile("cp.async.commit_group;" ::: "memory")
#define CP_WAIT(n) asm volatile("cp.async.wait_group %0;" ::"n"(n) : "memory")

__device__ __forceinline__ void ldsm_x4(uint32_t* r, uint32_t addr) {
    asm volatile(
        "ldmatrix.sync.aligned.m8n8.x4.shared.b16 {%0,%1,%2,%3}, [%4];"
        : "=r"(r[0]), "=r"(r[1]), "=r"(r[2]), "=r"(r[3])
        : "r"(addr));
}
__device__ __forceinline__ void mma_f16(float* c, const uint32_t* a,
                                        const uint32_t* b) {
    asm volatile(
        "mma.sync.aligned.m16n8k16.row.col.f32.f16.f16.f32 "
        "{%0,%1,%2,%3}, {%4,%5,%6,%7}, {%8,%9}, {%0,%1,%2,%3};"
        : "+f"(c[0]), "+f"(c[1]), "+f"(c[2]), "+f"(c[3])
        : "r"(a[0]), "r"(a[1]), "r"(a[2]), "r"(a[3]), "r"(b[0]), "r"(b[1]));
}

// ---------------- convert seq (fp32->fp16) + init losses --------------------
__global__ void __launch_bounds__(256) convert_init_kernel(
    const float* __restrict__ src, __half* __restrict__ dst) {
    const int i = (blockIdx.x * 256 + threadIdx.x) * 8;
    float4 v0 = *(const float4*)(src + i);
    float4 v1 = *(const float4*)(src + i + 4);
    __half2 h[4];
    h[0] = __floats2half2_rn(v0.x, v0.y);
    h[1] = __floats2half2_rn(v0.z, v0.w);
    h[2] = __floats2half2_rn(v1.x, v1.y);
    h[3] = __floats2half2_rn(v1.z, v1.w);
    *(uint4*)(dst + i) = *(uint4*)h;

    const int idx = blockIdx.x * 256 + threadIdx.x;
    if (idx < 4) g_losses[idx] = 0.f;
}

// ------ all 4 weight transposes + correction-row fp16 convert in one launch --
__global__ void transpose4_kernel(const float* __restrict__ pw1,
                                  const float* __restrict__ fw1,
                                  const float* __restrict__ pw2,
                                  const float* __restrict__ fw2) {
    __shared__ float t[32][33];
    const int z = blockIdx.z;
    if (z == 4) {
        const int row = blockIdx.y * 8 + threadIdx.y;
        if (row >= 24) return;
        const int col = blockIdx.x * 32 + threadIdx.x;
        const float* src = (row < 9) ? (pw1 + (512 + row) * 512)
                                     : (fw1 + (512 + row - 9) * 512);
        g_wc_h[row * 512 + col] = __float2half_rn(src[col]);
        return;
    }
    const float* src;
    __half* dst;
    int N;
    if (z == 0) { src = pw1; dst = g_wt_p1; N = 512; }
    else if (z == 1) { src = fw1; dst = g_wt_f1; N = 512; }
    else if (z == 2) { src = pw2; dst = g_wt_p2; N = 256; }
    else { src = fw2; dst = g_wt_f2; N = 512; }
    if (blockIdx.x * 32 >= N) return;

    const int n0 = blockIdx.x * 32, k0 = blockIdx.y * 32;
#pragma unroll
    for (int i = 0; i < 4; i++)
        t[threadIdx.y + i * 8][threadIdx.x] =
            src[(k0 + threadIdx.y + i * 8) * N + n0 + threadIdx.x];
    __syncthreads();
#pragma unroll
    for (int i = 0; i < 4; i++)
        dst[(n0 + threadIdx.y + i * 8) * 512 + k0 + threadIdx.x] =
            __float2half_rn(t[threadIdx.x][threadIdx.y + i * 8]);
}

// ---------------- fp16 tensor-core GEMM, dual-problem, 3-stage pipeline -----
// mode 0: store C fp16. mode 1: store with gelu.
// mode 2: gelu + reduce vs w3 (width 1). mode 3: gelu + reduce width 2.
#define STG 20480   // per stage: A 128*80 + B 128*80
__global__ void __launch_bounds__(256, 2) gemm_dual(
    const __half* __restrict__ Ap, const __half* __restrict__ Wtp,
    const float* __restrict__ biasp, void* __restrict__ outp, int Np,
    int nbp, int modep, const float* __restrict__ w3p,
    const __half* __restrict__ Af, const __half* __restrict__ Wtf,
    const float* __restrict__ biasf, void* __restrict__ outf, int Nf,
    int modef, const float* __restrict__ w3f)
{
    extern __shared__ __align__(16) unsigned char smraw[];
    const uint32_t sb = smem_u32(smraw);

    int bx = blockIdx.x;
    const __half* A;
    const __half* Wt;
    const float* bias;
    const float* w3;
    void* outpt;
    int N, mode;
    if (bx < nbp) {
        A = Ap; Wt = Wtp; bias = biasp; outpt = outp; N = Np; mode = modep;
        w3 = w3p;
    } else {
        bx -= nbp;
        A = Af; Wt = Wtf; bias = biasf; outpt = outf; N = Nf; mode = modef;
        w3 = w3f;
    }

    const int tid = threadIdx.x;
    const int lane = tid & 31;
    const int wid = tid >> 5;
    const int warp_m = wid >> 2;
    const int warp_n = wid & 3;
    const int brow = blockIdx.y * 128;
    const int bcol = bx * 128;

    const __half* Ab = A + (size_t)brow * 512;
    const __half* Bb = Wt + (size_t)bcol * 512;

    float acc[4][4][4];
#pragma unroll
    for (int i = 0; i < 4; i++)
#pragma unroll
        for (int j = 0; j < 4; j++)
#pragma unroll
            for (int k = 0; k < 4; k++) acc[i][j][k] = 0.f;

#define LOAD_TILE(cidx, stg)                                                  \
    do {                                                                      \
        const int kc = (cidx) * 32;                                           \
        const uint32_t base = sb + (stg) * STG;                               \
        _Pragma("unroll")                                                     \
        for (int i = 0; i < 2; i++) {                                         \
            const int lin = tid + i * 256;                                    \
            const int r = lin >> 2, ch = lin & 3;                             \
            cp_async16(base + r * 80 + ch * 16,                               \
                       Ab + (size_t)r * 512 + kc + ch * 8);                   \
            cp_async16(base + 10240 + r * 80 + ch * 16,                       \
                       Bb + (size_t)r * 512 + kc + ch * 8);                   \
        }                                                                     \
    } while (0)

    LOAD_TILE(0, 0);
    CP_COMMIT();
    LOAD_TILE(1, 1);
    CP_COMMIT();

    const uint32_t a_off =
        (uint32_t)(warp_m * 64 + (lane & 15)) * 80 + ((lane >> 4) << 4);
    const uint32_t b_off = 10240 +
        (uint32_t)(warp_n * 32 + ((lane >> 4) << 3) + (lane & 7)) * 80 +
        (((lane >> 3) & 1) << 4);

    int stg = 0;
#pragma unroll 1
    for (int c = 0; c < 16; c++) {
        if (c < 14) CP_WAIT(1); else CP_WAIT(0);
        __syncthreads();
        const uint32_t sbuf = sb + stg * STG;

#pragma unroll
        for (int ks = 0; ks < 2; ks++) {
            uint32_t a[4][4], b[4][2];
#pragma unroll
            for (int mf = 0; mf < 4; mf++)
                ldsm_x4(a[mf], sbuf + a_off + mf * (16 * 80) + ks * 32);
#pragma unroll
            for (int g = 0; g < 2; g++) {
                uint32_t r[4];
                ldsm_x4(r, sbuf + b_off + g * (16 * 80) + ks * 32);
                b[g * 2][0] = r[0]; b[g * 2][1] = r[1];
                b[g * 2 + 1][0] = r[2]; b[g * 2 + 1][1] = r[3];
            }
#pragma unroll
            for (int mf = 0; mf < 4; mf++)
#pragma unroll
                for (int nf = 0; nf < 4; nf++)
                    mma_f16(acc[mf][nf], a[mf], b[nf]);
        }

        if (c < 14) {
            const int nstg = (stg + 2 > 2) ? stg - 1 : stg + 2;
            LOAD_TILE(c + 2, nstg);
            CP_COMMIT();
        }
        stg = (stg + 1 > 2) ? 0 : stg + 1;
    }

    const int erow = warp_m * 64 + (lane >> 2);
    const int ecol = warp_n * 32 + (lane & 3) * 2;

    if (mode < 2) {
        __half* C = (__half*)outpt;
#pragma unroll
        for (int nf = 0; nf < 4; nf++) {
            const int col = bcol + ecol + nf * 8;
            const float2 bv = *(const float2*)(bias + col);
#pragma unroll
            for (int mf = 0; mf < 4; mf++) {
                float x0 = acc[mf][nf][0] + bv.x;
                float x1 = acc[mf][nf][1] + bv.y;
                float x2 = acc[mf][nf][2] + bv.x;
                float x3 = acc[mf][nf][3] + bv.y;
                if (mode == 1) {
                    x0 = gelu_exact(x0); x1 = gelu_exact(x1);
                    x2 = gelu_exact(x2); x3 = gelu_exact(x3);
                }
                const int r0 = brow + erow + mf * 16;
                *(__half2*)(C + (size_t)r0 * N + col) =
                    __floats2half2_rn(x0, x1);
                *(__half2*)(C + (size_t)(r0 + 8) * N + col) =
                    __floats2half2_rn(x2, x3);
            }
        }
    } else {
        float ps[4][2][2];
#pragma unroll
        for (int i = 0; i < 4; i++)
#pragma unroll
            for (int j = 0; j < 2; j++) { ps[i][j][0] = 0.f; ps[i][j][1] = 0.f; }

#pragma unroll
        for (int nf = 0; nf < 4; nf++) {
            const int col = bcol + ecol + nf * 8;
            const float2 bv = *(const float2*)(bias + col);
            float w3a0, w3b0, w3a1, w3b1;
            if (mode == 3) {
                const float4 w = __ldg((const float4*)(w3 + 2 * col));
                w3a0 = w.x; w3b0 = w.y; w3a1 = w.z; w3b1 = w.w;
            } else {
                const float2 w = __ldg((const float2*)(w3 + col));
                w3a0 = w.x; w3a1 = w.y; w3b0 = 0.f; w3b1 = 0.f;
            }
#pragma unroll
            for (int mf = 0; mf < 4; mf++) {
                const float x0 = gelu_exact(acc[mf][nf][0] + bv.x);
                const float x1 = gelu_exact(acc[mf][nf][1] + bv.y);
                const float x2 = gelu_exact(acc[mf][nf][2] + bv.x);
                const float x3 = gelu_exact(acc[mf][nf][3] + bv.y);
                ps[mf][0][0] += x0 * w3a0 + x1 * w3a1;
                ps[mf][0][1] += x0 * w3b0 + x1 * w3b1;
                ps[mf][1][0] += x2 * w3a0 + x3 * w3a1;
                ps[mf][1][1] += x2 * w3b0 + x3 * w3b1;
            }
        }
#pragma unroll
        for (int mf = 0; mf < 4; mf++)
#pragma unroll
            for (int pr = 0; pr < 2; pr++)
#pragma unroll
                for (int v = 0; v < 2; v++) {
                    float s = ps[mf][pr][v];
                    s += __shfl_xor_sync(0xffffffffu, s, 1);
                    s += __shfl_xor_sync(0xffffffffu, s, 2);
                    ps[mf][pr][v] = s;
                }

        float* red = (float*)smraw;
        __syncthreads();
        if ((lane & 3) == 0) {
#pragma unroll
            for (int mf = 0; mf < 4; mf++)
#pragma unroll
                for (int pr = 0; pr < 2; pr++) {
                    const int rc = warp_m * 64 + mf * 16 + pr * 8 + (lane >> 2);
                    float2 v = {ps[mf][pr][0], ps[mf][pr][1]};
                    *(float2*)&red[(warp_n * 128 + rc) * 2] = v;
                }
        }
        __syncthreads();
        if (tid < 128) {
            float2 s = {0.f, 0.f};
#pragma unroll
            for (int wn = 0; wn < 4; wn++) {
                const float2 v = *(const float2*)&red[(wn * 128 + tid) * 2];
                s.x += v.x; s.y += v.y;
            }
            float* part = (float*)outpt;
            *(float2*)&part[((size_t)bx * BB + brow + tid) * 2] = s;
        }
    }
}

// ---------------- build h1 v4: sparse state (only filled slots) -------------
__global__ void __launch_bounds__(256) build_h1_kernel(
    const int* __restrict__ perm_idx, int step)
{
    const int tid = threadIdx.x;
    const int rh = tid >> 7;
    const int lt = tid & 127;
    const int b = blockIdx.x * 2 + rh;
    const int n0 = lt * 4;
    const int pi = __ldg(&perm_idx[b]);
    const int ridx = c_perms[pi][step];

    float a0, a1, a2, a3;   // pres accumulator (4 cols)
    float f0, f1, f2, f3;   // full accumulator

#define LD4H(dst0, dst1, dst2, dst3, ptr)                                     \
    do {                                                                      \
        const uint2 _w = __ldg((const uint2*)(ptr));                          \
        const float2 _w01 = __half22float2(*(const __half2*)&_w.x);           \
        const float2 _w23 = __half22float2(*(const __half2*)&_w.y);           \
        dst0 = _w01.x; dst1 = _w01.y; dst2 = _w23.x; dst3 = _w23.y;           \
    } while (0)

    // base + onehot
    {
        float b0, b1, b2, b3, w0, w1, w2, w3;
        LD4H(b0, b1, b2, b3, &g_base_p[b * 512 + n0]);
        LD4H(w0, w1, w2, w3, &g_wc_h[(6 + ridx) * 512 + n0]);
        a0 = b0 + w0; a1 = b1 + w1; a2 = b2 + w2; a3 = b3 + w3;
        LD4H(b0, b1, b2, b3, &g_base_f[b * 512 + n0]);
        LD4H(w0, w1, w2, w3, &g_wc_h[(21 + ridx) * 512 + n0]);
        f0 = b0 + w0; f1 = b1 + w1; f2 = b2 + w2; f3 = b3 + w3;
    }

    // filled slots only (t < step); slot values from full_state float4
#pragma unroll 2
    for (int t = 0; t < step; t++) {
        const int r = c_perms[pi][t];
        const float4 fv = __ldg((const float4*)&g_full_state[b * 12 + 4 * r]);
        // fv = {act_f, act_p, act_e, 1}
        float w0, w1, w2, w3;
        // pres: val row 2r (× act_p), one row 2r+1 (+)
        LD4H(w0, w1, w2, w3, &g_wc_h[(2 * r) * 512 + n0]);
        a0 = fmaf(fv.y, w0, a0); a1 = fmaf(fv.y, w1, a1);
        a2 = fmaf(fv.y, w2, a2); a3 = fmaf(fv.y, w3, a3);
        LD4H(w0, w1, w2, w3, &g_wc_h[(2 * r + 1) * 512 + n0]);
        a0 += w0; a1 += w1; a2 += w2; a3 += w3;
        // full: rows 9+4r (act_f), +1 (act_p), +2 (act_e), +3 (one)
        LD4H(w0, w1, w2, w3, &g_wc_h[(9 + 4 * r) * 512 + n0]);
        f0 = fmaf(fv.x, w0, f0); f1 = fmaf(fv.x, w1, f1);
        f2 = fmaf(fv.x, w2, f2); f3 = fmaf(fv.x, w3, f3);
        LD4H(w0, w1, w2, w3, &g_wc_h[(9 + 4 * r + 1) * 512 + n0]);
        f0 = fmaf(fv.y, w0, f0); f1 = fmaf(fv.y, w1, f1);
        f2 = fmaf(fv.y, w2, f2); f3 = fmaf(fv.y, w3, f3);
        LD4H(w0, w1, w2, w3, &g_wc_h[(9 + 4 * r + 2) * 512 + n0]);
        f0 = fmaf(fv.z, w0, f0); f1 = fmaf(fv.z, w1, f1);
        f2 = fmaf(fv.z, w2, f2); f3 = fmaf(fv.z, w3, f3);
        LD4H(w0, w1, w2, w3, &g_wc_h[(9 + 4 * r + 3) * 512 + n0]);
        f0 += w0; f1 += w1; f2 += w2; f3 += w3;
    }

    {
        __half2 o01 = __floats2half2_rn(gelu_exact(a0), gelu_exact(a1));
        __half2 o23 = __floats2half2_rn(gelu_exact(a2), gelu_exact(a3));
        uint2 o;
        o.x = *(uint32_t*)&o01; o.y = *(uint32_t*)&o23;
        *(uint2*)&g_h1_p[b * 512 + n0] = o;
    }
    {
        __half2 o01 = __floats2half2_rn(gelu_exact(f0), gelu_exact(f1));
        __half2 o23 = __floats2half2_rn(gelu_exact(f2), gelu_exact(f3));
        uint2 o;
        o.x = *(uint32_t*)&o01; o.y = *(uint32_t*)&o23;
        *(uint2*)&g_h1_f[b * 512 + n0] = o;
    }
#undef LD4H
}

// ---------------- head scalar: combine partials, losses, state update -------
__global__ void __launch_bounds__(256) head_scalar_kernel(
    const float* __restrict__ pb3, const float* __restrict__ fb3,
    const float* __restrict__ freq, const float* __restrict__ pres,
    const float* __restrict__ enrich, const int* __restrict__ perm_idx,
    const int* __restrict__ round_mask, float* __restrict__ out, int step)
{
    __shared__ float blk[4];
    const int tid = threadIdx.x;
    if (tid < 4) blk[tid] = 0.f;
    __syncthreads();

    const int b = blockIdx.x * 256 + tid;

    float pp = g_part_p[(size_t)b * 2] + g_part_p[((size_t)BB + b) * 2] +
               pb3[0];
    float pf = fb3[0], pe = fb3[1];
#pragma unroll
    for (int j = 0; j < 4; j++) {
        pf += g_part_f[((size_t)j * BB + b) * 2];
        pe += g_part_f[((size_t)j * BB + b) * 2 + 1];
    }

    const int ridx = c_perms[perm_idx[b]][step];
    const float m = (float)round_mask[b * 3 + ridx];
    const float gt_f = freq[b * 3 + ridx];
    const float gt_p = pres[b * 3 + ridx];
    const float gt_e = enrich[b * 3 + ridx];

    float dlf = (pf - gt_f) * (pf - gt_f) * m;
    const float bce = fmaxf(pp, 0.f) - pp * gt_p + log1pf(expf(-fabsf(pp)));
    float dlp = bce * m;
    float dle = (pe - gt_e) * (pe - gt_e) * m;
    float dm = m;

    const bool msk = m > 0.5f;
    const float act_f = msk ? fminf(fmaxf(pf, -10.f), 10.f) : gt_f;
    const float act_p = msk ? (1.f / (1.f + expf(-pp))) : gt_p;
    const float act_e = msk ? fminf(fmaxf(pe, -100.f), 100.f) : gt_e;

    float4 fs = {act_f, act_p, act_e, 1.f};
    *(float4*)&g_full_state[b * 12 + 4 * ridx] = fs;

    out[3 + b * 3 + ridx] = act_f;
    out[3 + 3 * BB + b * 3 + ridx] = act_p;
    out[3 + 6 * BB + b * 3 + ridx] = act_e;

#pragma unroll
    for (int o = 16; o > 0; o >>= 1) {
        dlf += __shfl_xor_sync(0xffffffffu, dlf, o);
        dlp += __shfl_xor_sync(0xffffffffu, dlp, o);
        dle += __shfl_xor_sync(0xffffffffu, dle, o);
        dm  += __shfl_xor_sync(0xffffffffu, dm, o);
    }
    if ((tid & 31) == 0) {
        atomicAdd(&blk[0], dlf);
        atomicAdd(&blk[1], dlp);
        atomicAdd(&blk[2], dle);
        atomicAdd(&blk[3], dm);
    }
    __syncthreads();
    if (tid < 4) atomicAdd(&g_losses[tid], blk[tid]);
}

__global__ void finalize_kernel(float* __restrict__ out) {
    if (threadIdx.x == 0 && blockIdx.x == 0) {
        const float nm = g_losses[3] + 1e-8f;
        out[0] = g_losses[0] / nm;
        out[1] = g_losses[1] / nm;
        out[2] = g_losses[2] / nm;
    }
}

// ---------------- launcher --------------------------------------------------
extern "C" void kernel_launch(void* const* d_in, const int* in_sizes, int n_in,
                              void* d_out, int out_size)
{
    const float* seq      = (const float*)d_in[0];
    const float* freq     = (const float*)d_in[1];
    const float* pres     = (const float*)d_in[2];
    const float* enrich   = (const float*)d_in[3];
    const float* pw1      = (const float*)d_in[4];
    const float* pb1      = (const float*)d_in[5];
    const float* pw2      = (const float*)d_in[6];
    const float* pb2      = (const float*)d_in[7];
    const float* pw3      = (const float*)d_in[8];
    const float* pb3      = (const float*)d_in[9];
    const float* fw1      = (const float*)d_in[10];
    const float* fb1      = (const float*)d_in[11];
    const float* fw2      = (const float*)d_in[12];
    const float* fb2      = (const float*)d_in[13];
    const float* fw3      = (const float*)d_in[14];
    const float* fb3      = (const float*)d_in[15];
    const int*   perm_idx = (const int*)d_in[16];
    const int*   rmask    = (const int*)d_in[17];
    float* out = (float*)d_out;

    __half *seq_h, *base_p, *base_f, *h1_p, *h1_f;
    __half *wt_p1, *wt_f1, *wt_p2, *wt_f2;
    float *part_p, *part_f;
    cudaGetSymbolAddress((void**)&seq_h, g_seq_h);
    cudaGetSymbolAddress((void**)&base_p, g_base_p);
    cudaGetSymbolAddress((void**)&base_f, g_base_f);
    cudaGetSymbolAddress((void**)&h1_p, g_h1_p);
    cudaGetSymbolAddress((void**)&h1_f, g_h1_f);
    cudaGetSymbolAddress((void**)&wt_p1, g_wt_p1);
    cudaGetSymbolAddress((void**)&wt_f1, g_wt_f1);
    cudaGetSymbolAddress((void**)&wt_p2, g_wt_p2);
    cudaGetSymbolAddress((void**)&wt_f2, g_wt_f2);
    cudaGetSymbolAddress((void**)&part_p, g_part_p);
    cudaGetSymbolAddress((void**)&part_f, g_part_f);

    cudaFuncSetAttribute(gemm_dual,
                         cudaFuncAttributeMaxDynamicSharedMemorySize,
                         3 * STG);

    convert_init_kernel<<<BB * 512 / (256 * 8), 256>>>(seq, seq_h);
    transpose4_kernel<<<dim3(16, 16, 5), dim3(32, 8)>>>(pw1, fw1, pw2, fw2);

    // step-invariant base: seq @ W1[:512] + b1 (NO gelu); both branches fused
    gemm_dual<<<dim3(8, 128), 256, 3 * STG>>>(
        seq_h, wt_p1, pb1, base_p, 512, 4, 0, nullptr,
        seq_h, wt_f1, fb1, base_f, 512, 0, nullptr);

    for (int step = 0; step < 3; step++) {
        build_h1_kernel<<<BB / 2, 256>>>(perm_idx, step);
        gemm_dual<<<dim3(6, 128), 256, 3 * STG>>>(
            h1_p, wt_p2, pb2, part_p, 256, 2, 2, pw3,
            h1_f, wt_f2, fb2, part_f, 512, 3, fw3);
        head_scalar_kernel<<<BB / 256, 256>>>(pb3, fb3, freq, pres, enrich,
                                              perm_idx, rmask, out, step);
    }

    finalize_kernel<<<1, 32>>>(out);
}